// round 1
// baseline (speedup 1.0000x reference)
#include <cuda_runtime.h>

#define NN 100000
#define NE 600000
#define D  128
#define TE 64
#define SXS_E 388   // 384 + 4 pad (stride % 32 == 4 -> conflict-free x reads)
#define SXS_N 260   // 256 + 4 pad
#define SHS   132   // 128 + 4 pad

// Scratch for segment-sum aggregation (no cudaMalloc allowed).
__device__ float g_agg[(size_t)NN * D];

__global__ void zero_agg_kernel() {
    size_t i = (size_t)blockIdx.x * blockDim.x + threadIdx.x;
    ((float4*)g_agg)[i] = make_float4(0.f, 0.f, 0.f, 0.f);
}

// Tile GEMM: acc[4][8] += x[64 x K] (SMEM, row stride XS) * w[K x 128] (GMEM).
// Thread (ecg in 0..15, ccg in 0..15) owns edges ecg*4..+3, cols ccg*8..+7.
template <int K, int XS>
__device__ __forceinline__ void gemm_tile(const float* __restrict__ xs,
                                          const float* __restrict__ w,
                                          int ecg, int ccg, float acc[4][8]) {
    const float* wp = w + ccg * 8;
#pragma unroll
    for (int ei = 0; ei < 4; ei++) {
#pragma unroll
        for (int ci = 0; ci < 8; ci++) acc[ei][ci] = 0.f;
    }
#pragma unroll 4
    for (int k = 0; k < K; k++) {
        float4 wa = *(const float4*)(wp + (size_t)k * D);
        float4 wb = *(const float4*)(wp + (size_t)k * D + 4);
        float wr[8] = {wa.x, wa.y, wa.z, wa.w, wb.x, wb.y, wb.z, wb.w};
#pragma unroll
        for (int ei = 0; ei < 4; ei++) {
            float xv = xs[(ecg * 4 + ei) * XS + k];
#pragma unroll
            for (int ci = 0; ci < 8; ci++)
                acc[ei][ci] = fmaf(xv, wr[ci], acc[ei][ci]);
        }
    }
}

__device__ __forceinline__ void bias_relu_store(float acc[4][8],
                                                const float* __restrict__ b,
                                                float* __restrict__ sh,
                                                int ecg, int ccg) {
    float bv[8];
#pragma unroll
    for (int ci = 0; ci < 8; ci++) bv[ci] = b[ccg * 8 + ci];
#pragma unroll
    for (int ei = 0; ei < 4; ei++) {
#pragma unroll
        for (int ci = 0; ci < 8; ci++)
            sh[(ecg * 4 + ei) * SHS + ccg * 8 + ci] = fmaxf(acc[ei][ci] + bv[ci], 0.f);
    }
}

__global__ void __launch_bounds__(256, 1) edge_kernel(
    const float* __restrict__ nf, const float* __restrict__ ef,
    const int* __restrict__ senders, const int* __restrict__ receivers,
    const float* __restrict__ w1, const float* __restrict__ b1,
    const float* __restrict__ w2, const float* __restrict__ b2,
    const float* __restrict__ w3, const float* __restrict__ b3,
    const float* __restrict__ gamma, const float* __restrict__ beta,
    float* __restrict__ out_e)
{
    extern __shared__ float smem[];
    float* sx  = smem;                 // [TE][SXS_E]
    float* sh1 = smem + TE * SXS_E;    // [TE][SHS]
    float* sh2 = sh1 + TE * SHS;       // [TE][SHS]

    const int tid  = threadIdx.x;
    const int lane = tid & 31;
    const int wid  = tid >> 5;
    const int ccg  = tid & 15;
    const int ecg  = tid >> 4;
    const size_t base = (size_t)blockIdx.x * TE;

    // Gather x = [v_i | v_j | ef]: one warp per (edge, segment) row; 512B coalesced.
    for (int task = wid; task < 3 * TE; task += 8) {
        int e = task & (TE - 1);
        int seg = task >> 6;
        size_t ge = base + e;
        const float* src;
        if (seg == 0)      src = nf + (size_t)senders[ge] * D;
        else if (seg == 1) src = nf + (size_t)receivers[ge] * D;
        else               src = ef + ge * D;
        *(float4*)&sx[e * SXS_E + seg * D + lane * 4] = *(const float4*)(src + lane * 4);
    }
    __syncthreads();

    float acc[4][8];
    gemm_tile<384, SXS_E>(sx, w1, ecg, ccg, acc);
    bias_relu_store(acc, b1, sh1, ecg, ccg);
    __syncthreads();
    gemm_tile<128, SHS>(sh1, w2, ecg, ccg, acc);
    bias_relu_store(acc, b2, sh2, ecg, ccg);
    __syncthreads();
    gemm_tile<128, SHS>(sh2, w3, ecg, ccg, acc);

    float gv[8], bv[8], b3v[8];
#pragma unroll
    for (int ci = 0; ci < 8; ci++) {
        gv[ci]  = gamma[ccg * 8 + ci];
        bv[ci]  = beta[ccg * 8 + ci];
        b3v[ci] = b3[ccg * 8 + ci];
    }
#pragma unroll
    for (int ei = 0; ei < 4; ei++) {
        float s = 0.f, s2 = 0.f;
#pragma unroll
        for (int ci = 0; ci < 8; ci++) {
            acc[ei][ci] += b3v[ci];
            float v = acc[ei][ci];
            s += v; s2 += v * v;
        }
#pragma unroll
        for (int m = 8; m >= 1; m >>= 1) {
            s  += __shfl_xor_sync(0xffffffffu, s, m);
            s2 += __shfl_xor_sync(0xffffffffu, s2, m);
        }
        float mu   = s * (1.f / D);
        float var  = s2 * (1.f / D) - mu * mu;
        float rstd = rsqrtf(fmaxf(var, 0.f) + 1e-5f);

        int el = ecg * 4 + ei;
        size_t ge = base + el;
        int r = receivers[ge];
        float* ap = g_agg + (size_t)r * D + ccg * 8;

        float o[8];
#pragma unroll
        for (int ci = 0; ci < 8; ci++) {
            float nrm = (acc[ei][ci] - mu) * rstd * gv[ci] + bv[ci];
            atomicAdd(ap + ci, nrm);   // segment_sum(new_e, receivers)
            o[ci] = nrm + sx[el * SXS_E + 256 + ccg * 8 + ci];  // + edge_features
        }
        float* op = out_e + ge * D + ccg * 8;
        *(float4*)op       = make_float4(o[0], o[1], o[2], o[3]);
        *(float4*)(op + 4) = make_float4(o[4], o[5], o[6], o[7]);
    }
}

__global__ void __launch_bounds__(256, 1) node_kernel(
    const float* __restrict__ nf,
    const float* __restrict__ w1, const float* __restrict__ b1,
    const float* __restrict__ w2, const float* __restrict__ b2,
    const float* __restrict__ w3, const float* __restrict__ b3,
    const float* __restrict__ gamma, const float* __restrict__ beta,
    float* __restrict__ out_n)
{
    extern __shared__ float smem[];
    float* sx  = smem;                 // [TE][SXS_N]  (nf | agg; zeros block skipped)
    float* sh1 = smem + TE * SXS_N;
    float* sh2 = sh1 + TE * SHS;

    const int tid  = threadIdx.x;
    const int lane = tid & 31;
    const int wid  = tid >> 5;
    const int ccg  = tid & 15;
    const int ecg  = tid >> 4;
    const size_t base = (size_t)blockIdx.x * TE;

    for (int task = wid; task < 2 * TE; task += 8) {
        int e = task & (TE - 1);
        int seg = task >> 6;
        size_t ge = base + e;
        float4 v = make_float4(0.f, 0.f, 0.f, 0.f);
        if (ge < NN) {
            const float* src = (seg == 0) ? (nf + ge * D) : (g_agg + ge * D);
            v = *(const float4*)(src + lane * 4);
        }
        *(float4*)&sx[e * SXS_N + seg * D + lane * 4] = v;
    }
    __syncthreads();

    float acc[4][8];
    gemm_tile<256, SXS_N>(sx, w1, ecg, ccg, acc);   // rows 256..383 of w1 hit zeros -> skip
    bias_relu_store(acc, b1, sh1, ecg, ccg);
    __syncthreads();
    gemm_tile<128, SHS>(sh1, w2, ecg, ccg, acc);
    bias_relu_store(acc, b2, sh2, ecg, ccg);
    __syncthreads();
    gemm_tile<128, SHS>(sh2, w3, ecg, ccg, acc);

    float gv[8], bv[8], b3v[8];
#pragma unroll
    for (int ci = 0; ci < 8; ci++) {
        gv[ci]  = gamma[ccg * 8 + ci];
        bv[ci]  = beta[ccg * 8 + ci];
        b3v[ci] = b3[ccg * 8 + ci];
    }
#pragma unroll
    for (int ei = 0; ei < 4; ei++) {
        float s = 0.f, s2 = 0.f;
#pragma unroll
        for (int ci = 0; ci < 8; ci++) {
            acc[ei][ci] += b3v[ci];
            float v = acc[ei][ci];
            s += v; s2 += v * v;
        }
#pragma unroll
        for (int m = 8; m >= 1; m >>= 1) {
            s  += __shfl_xor_sync(0xffffffffu, s, m);
            s2 += __shfl_xor_sync(0xffffffffu, s2, m);
        }
        float mu   = s * (1.f / D);
        float var  = s2 * (1.f / D) - mu * mu;
        float rstd = rsqrtf(fmaxf(var, 0.f) + 1e-5f);

        int el = ecg * 4 + ei;
        size_t ge = base + el;
        if (ge < NN) {
            float o[8];
#pragma unroll
            for (int ci = 0; ci < 8; ci++) {
                float nrm = (acc[ei][ci] - mu) * rstd * gv[ci] + bv[ci];
                o[ci] = nrm + sx[el * SXS_N + ccg * 8 + ci];  // + node_features
            }
            float* op = out_n + ge * D + ccg * 8;
            *(float4*)op       = make_float4(o[0], o[1], o[2], o[3]);
            *(float4*)(op + 4) = make_float4(o[4], o[5], o[6], o[7]);
        }
    }
}

extern "C" void kernel_launch(void* const* d_in, const int* in_sizes, int n_in,
                              void* d_out, int out_size) {
    const float* nf  = (const float*)d_in[0];
    const float* ef  = (const float*)d_in[1];
    const int*   snd = (const int*)d_in[2];
    const int*   rcv = (const int*)d_in[3];
    const float* ew1 = (const float*)d_in[4];
    const float* eb1 = (const float*)d_in[5];
    const float* ew2 = (const float*)d_in[6];
    const float* eb2 = (const float*)d_in[7];
    const float* ew3 = (const float*)d_in[8];
    const float* eb3 = (const float*)d_in[9];
    const float* eg  = (const float*)d_in[10];
    const float* ebt = (const float*)d_in[11];
    const float* nw1 = (const float*)d_in[12];
    const float* nb1 = (const float*)d_in[13];
    const float* nw2 = (const float*)d_in[14];
    const float* nb2 = (const float*)d_in[15];
    const float* nw3 = (const float*)d_in[16];
    const float* nb3 = (const float*)d_in[17];
    const float* ng  = (const float*)d_in[18];
    const float* nbt = (const float*)d_in[19];

    float* out_n = (float*)d_out;                   // (1, N, D) first
    float* out_e = out_n + (size_t)NN * D;          // then (1, E, D)

    const int edge_smem = (TE * SXS_E + 2 * TE * SHS) * (int)sizeof(float); // 166912 B
    const int node_smem = (TE * SXS_N + 2 * TE * SHS) * (int)sizeof(float); // 134144 B
    cudaFuncSetAttribute(edge_kernel, cudaFuncAttributeMaxDynamicSharedMemorySize, edge_smem);
    cudaFuncSetAttribute(node_kernel, cudaFuncAttributeMaxDynamicSharedMemorySize, node_smem);

    zero_agg_kernel<<<NN * D / 4 / 256, 256>>>();
    edge_kernel<<<NE / TE, 256, edge_smem>>>(nf, ef, snd, rcv,
                                             ew1, eb1, ew2, eb2, ew3, eb3,
                                             eg, ebt, out_e);
    node_kernel<<<(NN + TE - 1) / TE, 256, node_smem>>>(nf,
                                                        nw1, nb1, nw2, nb2, nw3, nb3,
                                                        ng, nbt, out_n);
}

// round 2
// speedup vs baseline: 2.2632x; 2.2632x over previous
#include <cuda_runtime.h>
#include <cuda_bf16.h>
#include <cstdint>

#define NN 100000
#define NE 600000
#define D  128
#define WPAD 136            // padded weight/h row width (272B rows: %128 == 16)

// ---------------- global scratch (no cudaMalloc allowed) ----------------
__device__ float g_agg[(size_t)NN * D];
// pre-split weights, bf16 hi/lo planes, rows stacked:
// [0,384) ew1 | [384,512) ew2 | [512,640) ew3 | [640,896) nw1[0:256] | [896,1024) nw2 | [1024,1152) nw3
__device__ __nv_bfloat16 g_w_hi[1152 * WPAD];
__device__ __nv_bfloat16 g_w_lo[1152 * WPAD];

__global__ void zero_agg_kernel() {
    size_t i = (size_t)blockIdx.x * blockDim.x + threadIdx.x;
    ((float4*)g_agg)[i] = make_float4(0.f, 0.f, 0.f, 0.f);
}

__global__ void prep_weights(const float* __restrict__ ew1, const float* __restrict__ ew2,
                             const float* __restrict__ ew3, const float* __restrict__ nw1,
                             const float* __restrict__ nw2, const float* __restrict__ nw3) {
    int idx = blockIdx.x * 256 + threadIdx.x;
    if (idx >= 1152 * WPAD) return;
    int r = idx / WPAD, c = idx % WPAD;
    float v = 0.f;
    if (c < 128) {
        if (r < 384)       v = ew1[r * 128 + c];
        else if (r < 512)  v = ew2[(r - 384) * 128 + c];
        else if (r < 640)  v = ew3[(r - 512) * 128 + c];
        else if (r < 896)  v = nw1[(r - 640) * 128 + c];
        else if (r < 1024) v = nw2[(r - 896) * 128 + c];
        else               v = nw3[(r - 1024) * 128 + c];
    }
    __nv_bfloat16 h = __float2bfloat16(v);
    g_w_hi[idx] = h;
    g_w_lo[idx] = __float2bfloat16(v - __bfloat162float(h));
}

// ---------------- mma / ldmatrix helpers ----------------
__device__ __forceinline__ void mma16816(float* c, const uint32_t* a, const uint32_t* b) {
    asm volatile(
        "mma.sync.aligned.m16n8k16.row.col.f32.bf16.bf16.f32 "
        "{%0,%1,%2,%3}, {%4,%5,%6,%7}, {%8,%9}, {%0,%1,%2,%3};"
        : "+f"(c[0]), "+f"(c[1]), "+f"(c[2]), "+f"(c[3])
        : "r"(a[0]), "r"(a[1]), "r"(a[2]), "r"(a[3]), "r"(b[0]), "r"(b[1]));
}
__device__ __forceinline__ void ldm_a(uint32_t* r, uint32_t addr) {
    asm volatile("ldmatrix.sync.aligned.m8n8.x4.shared.b16 {%0,%1,%2,%3}, [%4];"
                 : "=r"(r[0]), "=r"(r[1]), "=r"(r[2]), "=r"(r[3]) : "r"(addr));
}
__device__ __forceinline__ void ldm_bt(uint32_t* r, uint32_t addr) {
    asm volatile("ldmatrix.sync.aligned.m8n8.x2.trans.shared.b16 {%0,%1}, [%2];"
                 : "=r"(r[0]), "=r"(r[1]) : "r"(addr));
}
__device__ __forceinline__ uint32_t bpack(__nv_bfloat16 a, __nv_bfloat16 b) {
    __nv_bfloat162 t = __halves2bfloat162(a, b);
    return *reinterpret_cast<uint32_t*>(&t);
}
__device__ __forceinline__ void split_pack4(float4 v, uint2& hi, uint2& lo) {
    __nv_bfloat16 h0 = __float2bfloat16(v.x), h1 = __float2bfloat16(v.y);
    __nv_bfloat16 h2 = __float2bfloat16(v.z), h3 = __float2bfloat16(v.w);
    hi.x = bpack(h0, h1); hi.y = bpack(h2, h3);
    lo.x = bpack(__float2bfloat16(v.x - __bfloat162float(h0)),
                 __float2bfloat16(v.y - __bfloat162float(h1)));
    lo.y = bpack(__float2bfloat16(v.z - __bfloat162float(h2)),
                 __float2bfloat16(v.w - __bfloat162float(h3)));
}

// GEMM: acc[2][4][4] = X[64 x KTOT] (split bf16 in smem) * W[KTOT x 128] (split bf16, staged chunks).
// 8 warps = 2(M) x 4(N); warp tile 32x32; 3 mma per tile pair (hi*hi + hi*lo + lo*hi).
template <int KTOT>
__device__ __forceinline__ void gemm_layer(char* smem, uint32_t sbase,
                                           uint32_t xh_off, uint32_t xl_off, int xsb,
                                           int wrow0, uint32_t wbh_off, uint32_t wbl_off,
                                           int tid, int lane, int wm, int wn,
                                           float acc[2][4][4]) {
#pragma unroll
    for (int mt = 0; mt < 2; mt++)
#pragma unroll
        for (int nt = 0; nt < 4; nt++)
#pragma unroll
            for (int i = 0; i < 4; i++) acc[mt][nt][i] = 0.f;

    const int nch = KTOT / 64;
    for (int ch = 0; ch < nch; ch++) {
        __syncthreads();
        const uint32_t* sh = (const uint32_t*)(g_w_hi + (size_t)(wrow0 + ch * 64) * WPAD);
        const uint32_t* sl = (const uint32_t*)(g_w_lo + (size_t)(wrow0 + ch * 64) * WPAD);
        uint32_t* dh = (uint32_t*)(smem + wbh_off);
        uint32_t* dl = (uint32_t*)(smem + wbl_off);
        for (int i = tid; i < 64 * WPAD / 2; i += 256) { dh[i] = __ldg(sh + i); dl[i] = __ldg(sl + i); }
        __syncthreads();

#pragma unroll
        for (int ks = 0; ks < 4; ks++) {
            const int kg = ch * 64 + ks * 16;
            uint32_t ah[2][4], al[2][4];
#pragma unroll
            for (int mt = 0; mt < 2; mt++) {
                uint32_t row  = wm * 32 + mt * 16 + (lane & 15);
                uint32_t colb = (uint32_t)(kg + ((lane >> 4) << 3)) * 2;
                ldm_a(ah[mt], sbase + xh_off + row * xsb + colb);
                ldm_a(al[mt], sbase + xl_off + row * xsb + colb);
            }
            uint32_t bh[4][2], bl[4][2];
            uint32_t brow = (uint32_t)(ks * 16 + (lane & 15)) * (WPAD * 2);
#pragma unroll
            for (int nt = 0; nt < 4; nt++) {
                uint32_t nb = (uint32_t)(wn * 32 + nt * 8) * 2;
                ldm_bt(bh[nt], sbase + wbh_off + brow + nb);
                ldm_bt(bl[nt], sbase + wbl_off + brow + nb);
            }
#pragma unroll
            for (int mt = 0; mt < 2; mt++)
#pragma unroll
                for (int nt = 0; nt < 4; nt++) {
                    mma16816(acc[mt][nt], ah[mt], bh[nt]);
                    mma16816(acc[mt][nt], ah[mt], bl[nt]);
                    mma16816(acc[mt][nt], al[mt], bh[nt]);
                }
        }
    }
}

// epilogue: bias + relu, split to bf16 hi/lo h-planes (row stride 272B)
__device__ __forceinline__ void epi_relu_split(float acc[2][4][4], const float* __restrict__ bias,
                                               char* smem, uint32_t hh_off, uint32_t hl_off,
                                               int lane, int wm, int wn) {
#pragma unroll
    for (int mt = 0; mt < 2; mt++)
#pragma unroll
        for (int nt = 0; nt < 4; nt++) {
            int n0 = wn * 32 + nt * 8 + (lane & 3) * 2;
            float2 bv = *(const float2*)(bias + n0);
            int r0 = wm * 32 + mt * 16 + (lane >> 2);
            float v0 = fmaxf(acc[mt][nt][0] + bv.x, 0.f);
            float v1 = fmaxf(acc[mt][nt][1] + bv.y, 0.f);
            float v2 = fmaxf(acc[mt][nt][2] + bv.x, 0.f);
            float v3 = fmaxf(acc[mt][nt][3] + bv.y, 0.f);
            __nv_bfloat16 h0 = __float2bfloat16(v0), h1 = __float2bfloat16(v1);
            __nv_bfloat16 h2 = __float2bfloat16(v2), h3 = __float2bfloat16(v3);
            *(uint32_t*)(smem + hh_off + r0 * 272 + n0 * 2) = bpack(h0, h1);
            *(uint32_t*)(smem + hl_off + r0 * 272 + n0 * 2) =
                bpack(__float2bfloat16(v0 - __bfloat162float(h0)),
                      __float2bfloat16(v1 - __bfloat162float(h1)));
            *(uint32_t*)(smem + hh_off + (r0 + 8) * 272 + n0 * 2) = bpack(h2, h3);
            *(uint32_t*)(smem + hl_off + (r0 + 8) * 272 + n0 * 2) =
                bpack(__float2bfloat16(v2 - __bfloat162float(h2)),
                      __float2bfloat16(v3 - __bfloat162float(h3)));
        }
}

// epilogue layer3: bias only, fp32 to LN staging buffer (row stride 528B)
__device__ __forceinline__ void epi_f32(float acc[2][4][4], const float* __restrict__ bias,
                                        char* smem, uint32_t f_off, int lane, int wm, int wn) {
#pragma unroll
    for (int mt = 0; mt < 2; mt++)
#pragma unroll
        for (int nt = 0; nt < 4; nt++) {
            int n0 = wn * 32 + nt * 8 + (lane & 3) * 2;
            float2 bv = *(const float2*)(bias + n0);
            int r0 = wm * 32 + mt * 16 + (lane >> 2);
            *(float2*)(smem + f_off + r0 * 528 + n0 * 4) =
                make_float2(acc[mt][nt][0] + bv.x, acc[mt][nt][1] + bv.y);
            *(float2*)(smem + f_off + (r0 + 8) * 528 + n0 * 4) =
                make_float2(acc[mt][nt][2] + bv.x, acc[mt][nt][3] + bv.y);
        }
}

// ---------------- edge kernel ----------------
// smem layout (bytes): XH 0(50176) XL 50176 | H1H 100352 H1L 117760 | H2H 135168 H2L 152576 |
//                      WBH 169984 WBL 187392 | total 204800.  LN f32 buffer aliases XH (64*528=33792).
#define E_XH   0u
#define E_XL   50176u
#define E_H1H  100352u
#define E_H1L  117760u
#define E_H2H  135168u
#define E_H2L  152576u
#define E_WBH  169984u
#define E_WBL  187392u
#define E_SMEM 204800

__global__ void __launch_bounds__(256, 1) edge_kernel(
    const float* __restrict__ nf, const float* __restrict__ ef,
    const int* __restrict__ senders, const int* __restrict__ receivers,
    const float* __restrict__ b1, const float* __restrict__ b2, const float* __restrict__ b3,
    const float* __restrict__ gamma, const float* __restrict__ beta,
    float* __restrict__ out_e) {
    extern __shared__ char smem[];
    const uint32_t sbase = (uint32_t)__cvta_generic_to_shared(smem);
    const int tid = threadIdx.x, lane = tid & 31, wid = tid >> 5;
    const int wm = wid >> 2, wn = wid & 3;
    const size_t base = (size_t)blockIdx.x * 64;

    // gather x = [v_i | v_j | ef] -> bf16 hi/lo planes, row stride 784B
    for (int task = wid; task < 192; task += 8) {
        int e = task & 63, seg = task >> 6;
        size_t ge = base + e;
        const float* src;
        if (seg == 0)      src = nf + (size_t)senders[ge] * D;
        else if (seg == 1) src = nf + (size_t)receivers[ge] * D;
        else               src = ef + ge * D;
        float4 v = *(const float4*)(src + lane * 4);
        uint2 hi, lo; split_pack4(v, hi, lo);
        uint32_t off = (uint32_t)e * 784 + (uint32_t)(seg * 128 + lane * 4) * 2;
        *(uint2*)(smem + E_XH + off) = hi;
        *(uint2*)(smem + E_XL + off) = lo;
    }

    float acc[2][4][4];
    gemm_layer<384>(smem, sbase, E_XH, E_XL, 784, 0,   E_WBH, E_WBL, tid, lane, wm, wn, acc);
    epi_relu_split(acc, b1, smem, E_H1H, E_H1L, lane, wm, wn);
    gemm_layer<128>(smem, sbase, E_H1H, E_H1L, 272, 384, E_WBH, E_WBL, tid, lane, wm, wn, acc);
    epi_relu_split(acc, b2, smem, E_H2H, E_H2L, lane, wm, wn);
    gemm_layer<128>(smem, sbase, E_H2H, E_H2L, 272, 512, E_WBH, E_WBL, tid, lane, wm, wn, acc);
    epi_f32(acc, b3, smem, 0u, lane, wm, wn);   // aliases dead x region
    __syncthreads();

    // LN + segment-sum scatter + residual
    const int ccg = tid & 15, ecg = tid >> 4;
    float4 g0 = *(const float4*)(gamma + ccg * 8), g1 = *(const float4*)(gamma + ccg * 8 + 4);
    float4 t0 = *(const float4*)(beta + ccg * 8),  t1 = *(const float4*)(beta + ccg * 8 + 4);
    float gv[8] = {g0.x, g0.y, g0.z, g0.w, g1.x, g1.y, g1.z, g1.w};
    float bv[8] = {t0.x, t0.y, t0.z, t0.w, t1.x, t1.y, t1.z, t1.w};
#pragma unroll
    for (int ei = 0; ei < 4; ei++) {
        int el = ecg * 4 + ei;
        float4 p0 = *(float4*)(smem + (uint32_t)el * 528 + ccg * 32);
        float4 p1 = *(float4*)(smem + (uint32_t)el * 528 + ccg * 32 + 16);
        float v[8] = {p0.x, p0.y, p0.z, p0.w, p1.x, p1.y, p1.z, p1.w};
        float s = 0.f, s2 = 0.f;
#pragma unroll
        for (int c = 0; c < 8; c++) { s += v[c]; s2 += v[c] * v[c]; }
#pragma unroll
        for (int m = 8; m >= 1; m >>= 1) {
            s  += __shfl_xor_sync(0xffffffffu, s, m);
            s2 += __shfl_xor_sync(0xffffffffu, s2, m);
        }
        float mu = s * (1.f / D);
        float var = s2 * (1.f / D) - mu * mu;
        float rstd = rsqrtf(fmaxf(var, 0.f) + 1e-5f);
        size_t ge = base + el;
        int r = receivers[ge];
        float nrm[8];
#pragma unroll
        for (int c = 0; c < 8; c++) nrm[c] = (v[c] - mu) * rstd * gv[c] + bv[c];
        float* ap = g_agg + (size_t)r * D + ccg * 8;
        asm volatile("red.global.add.v4.f32 [%0], {%1,%2,%3,%4};" ::
                     "l"(ap), "f"(nrm[0]), "f"(nrm[1]), "f"(nrm[2]), "f"(nrm[3]) : "memory");
        asm volatile("red.global.add.v4.f32 [%0], {%1,%2,%3,%4};" ::
                     "l"(ap + 4), "f"(nrm[4]), "f"(nrm[5]), "f"(nrm[6]), "f"(nrm[7]) : "memory");
        const float4 e0 = *(const float4*)(ef + ge * D + ccg * 8);
        const float4 e1 = *(const float4*)(ef + ge * D + ccg * 8 + 4);
        float* op = out_e + ge * D + ccg * 8;
        *(float4*)op       = make_float4(nrm[0] + e0.x, nrm[1] + e0.y, nrm[2] + e0.z, nrm[3] + e0.w);
        *(float4*)(op + 4) = make_float4(nrm[4] + e1.x, nrm[5] + e1.y, nrm[6] + e1.z, nrm[7] + e1.w);
    }
}

// ---------------- node kernel ----------------
// smem: XH 0(33792) XL 33792 | H1H 67584 H1L 84992 | H2H 102400 H2L 119808 |
//       WBH 137216 WBL 154624 | total 172032.  LN buffer aliases XH.
#define N_XH   0u
#define N_XL   33792u
#define N_H1H  67584u
#define N_H1L  84992u
#define N_H2H  102400u
#define N_H2L  119808u
#define N_WBH  137216u
#define N_WBL  154624u
#define N_SMEM 172032

__global__ void __launch_bounds__(256, 1) node_kernel(
    const float* __restrict__ nf,
    const float* __restrict__ b1, const float* __restrict__ b2, const float* __restrict__ b3,
    const float* __restrict__ gamma, const float* __restrict__ beta,
    float* __restrict__ out_n) {
    extern __shared__ char smem[];
    const uint32_t sbase = (uint32_t)__cvta_generic_to_shared(smem);
    const int tid = threadIdx.x, lane = tid & 31, wid = tid >> 5;
    const int wm = wid >> 2, wn = wid & 3;
    const size_t base = (size_t)blockIdx.x * 64;

    for (int task = wid; task < 128; task += 8) {
        int e = task & 63, seg = task >> 6;
        size_t ge = base + e;
        float4 v = make_float4(0.f, 0.f, 0.f, 0.f);
        if (ge < NN) {
            const float* src = (seg == 0) ? (nf + ge * D) : (g_agg + ge * D);
            v = *(const float4*)(src + lane * 4);
        }
        uint2 hi, lo; split_pack4(v, hi, lo);
        uint32_t off = (uint32_t)e * 528 + (uint32_t)(seg * 128 + lane * 4) * 2;
        *(uint2*)(smem + N_XH + off) = hi;
        *(uint2*)(smem + N_XL + off) = lo;
    }

    float acc[2][4][4];
    gemm_layer<256>(smem, sbase, N_XH, N_XL, 528, 640,  N_WBH, N_WBL, tid, lane, wm, wn, acc);
    epi_relu_split(acc, b1, smem, N_H1H, N_H1L, lane, wm, wn);
    gemm_layer<128>(smem, sbase, N_H1H, N_H1L, 272, 896, N_WBH, N_WBL, tid, lane, wm, wn, acc);
    epi_relu_split(acc, b2, smem, N_H2H, N_H2L, lane, wm, wn);
    gemm_layer<128>(smem, sbase, N_H2H, N_H2L, 272, 1024, N_WBH, N_WBL, tid, lane, wm, wn, acc);
    epi_f32(acc, b3, smem, 0u, lane, wm, wn);
    __syncthreads();

    const int ccg = tid & 15, ecg = tid >> 4;
    float4 g0 = *(const float4*)(gamma + ccg * 8), g1 = *(const float4*)(gamma + ccg * 8 + 4);
    float4 t0 = *(const float4*)(beta + ccg * 8),  t1 = *(const float4*)(beta + ccg * 8 + 4);
    float gv[8] = {g0.x, g0.y, g0.z, g0.w, g1.x, g1.y, g1.z, g1.w};
    float bv[8] = {t0.x, t0.y, t0.z, t0.w, t1.x, t1.y, t1.z, t1.w};
#pragma unroll
    for (int ei = 0; ei < 4; ei++) {
        int el = ecg * 4 + ei;
        float4 p0 = *(float4*)(smem + (uint32_t)el * 528 + ccg * 32);
        float4 p1 = *(float4*)(smem + (uint32_t)el * 528 + ccg * 32 + 16);
        float v[8] = {p0.x, p0.y, p0.z, p0.w, p1.x, p1.y, p1.z, p1.w};
        float s = 0.f, s2 = 0.f;
#pragma unroll
        for (int c = 0; c < 8; c++) { s += v[c]; s2 += v[c] * v[c]; }
#pragma unroll
        for (int m = 8; m >= 1; m >>= 1) {
            s  += __shfl_xor_sync(0xffffffffu, s, m);
            s2 += __shfl_xor_sync(0xffffffffu, s2, m);
        }
        float mu = s * (1.f / D);
        float var = s2 * (1.f / D) - mu * mu;
        float rstd = rsqrtf(fmaxf(var, 0.f) + 1e-5f);
        size_t ge = base + el;
        if (ge < NN) {
            const float4 n0v = *(const float4*)(nf + ge * D + ccg * 8);
            const float4 n1v = *(const float4*)(nf + ge * D + ccg * 8 + 4);
            float nrm[8];
#pragma unroll
            for (int c = 0; c < 8; c++) nrm[c] = (v[c] - mu) * rstd * gv[c] + bv[c];
            float* op = out_n + ge * D + ccg * 8;
            *(float4*)op       = make_float4(nrm[0] + n0v.x, nrm[1] + n0v.y, nrm[2] + n0v.z, nrm[3] + n0v.w);
            *(float4*)(op + 4) = make_float4(nrm[4] + n1v.x, nrm[5] + n1v.y, nrm[6] + n1v.z, nrm[7] + n1v.w);
        }
    }
}

extern "C" void kernel_launch(void* const* d_in, const int* in_sizes, int n_in,
                              void* d_out, int out_size) {
    const float* nf  = (const float*)d_in[0];
    const float* ef  = (const float*)d_in[1];
    const int*   snd = (const int*)d_in[2];
    const int*   rcv = (const int*)d_in[3];
    const float* ew1 = (const float*)d_in[4];
    const float* eb1 = (const float*)d_in[5];
    const float* ew2 = (const float*)d_in[6];
    const float* eb2 = (const float*)d_in[7];
    const float* ew3 = (const float*)d_in[8];
    const float* eb3 = (const float*)d_in[9];
    const float* eg  = (const float*)d_in[10];
    const float* ebt = (const float*)d_in[11];
    const float* nw1 = (const float*)d_in[12];
    const float* nb1 = (const float*)d_in[13];
    const float* nw2 = (const float*)d_in[14];
    const float* nb2 = (const float*)d_in[15];
    const float* nw3 = (const float*)d_in[16];
    const float* nb3 = (const float*)d_in[17];
    const float* ng  = (const float*)d_in[18];
    const float* nbt = (const float*)d_in[19];

    float* out_n = (float*)d_out;
    float* out_e = out_n + (size_t)NN * D;

    cudaFuncSetAttribute(edge_kernel, cudaFuncAttributeMaxDynamicSharedMemorySize, E_SMEM);
    cudaFuncSetAttribute(node_kernel, cudaFuncAttributeMaxDynamicSharedMemorySize, N_SMEM);

    prep_weights<<<612, 256>>>(ew1, ew2, ew3, nw1, nw2, nw3);
    zero_agg_kernel<<<NN * D / 4 / 256, 256>>>();
    edge_kernel<<<NE / 64, 256, E_SMEM>>>(nf, ef, snd, rcv, eb1, eb2, eb3, eg, ebt, out_e);
    node_kernel<<<(NN + 63) / 64, 256, N_SMEM>>>(nf, nb1, nb2, nb3, ng, nbt, out_n);
}

// round 3
// speedup vs baseline: 3.5297x; 1.5596x over previous
#include <cuda_runtime.h>
#include <cuda_bf16.h>
#include <cstdint>

#define NN 100000
#define NE 600000
#define D  128
#define WPAD 136            // padded weight row width (272B rows: %128 == 16)
#define WCHUNK_B 8704       // 32 rows * 272B, per plane
#define WBUF_B   17408      // hi + lo planes per buffer

// ---------------- global scratch (no cudaMalloc allowed) ----------------
__device__ float g_agg[(size_t)NN * D];
// pre-split weights, bf16 hi/lo planes, rows stacked:
// [0,384) ew1 | [384,512) ew2 | [512,640) ew3 | [640,896) nw1[0:256] | [896,1024) nw2 | [1024,1152) nw3
__device__ __nv_bfloat16 g_w_hi[1152 * WPAD];
__device__ __nv_bfloat16 g_w_lo[1152 * WPAD];

__global__ void zero_agg_kernel() {
    size_t i = (size_t)blockIdx.x * blockDim.x + threadIdx.x;
    ((float4*)g_agg)[i] = make_float4(0.f, 0.f, 0.f, 0.f);
}

__global__ void prep_weights(const float* __restrict__ ew1, const float* __restrict__ ew2,
                             const float* __restrict__ ew3, const float* __restrict__ nw1,
                             const float* __restrict__ nw2, const float* __restrict__ nw3) {
    int idx = blockIdx.x * 256 + threadIdx.x;
    if (idx >= 1152 * WPAD) return;
    int r = idx / WPAD, c = idx % WPAD;
    float v = 0.f;
    if (c < 128) {
        if (r < 384)       v = ew1[r * 128 + c];
        else if (r < 512)  v = ew2[(r - 384) * 128 + c];
        else if (r < 640)  v = ew3[(r - 512) * 128 + c];
        else if (r < 896)  v = nw1[(r - 640) * 128 + c];
        else if (r < 1024) v = nw2[(r - 896) * 128 + c];
        else               v = nw3[(r - 1024) * 128 + c];
    }
    __nv_bfloat16 h = __float2bfloat16(v);
    g_w_hi[idx] = h;
    g_w_lo[idx] = __float2bfloat16(v - __bfloat162float(h));
}

// ---------------- mma / ldmatrix / cp.async helpers ----------------
__device__ __forceinline__ void mma16816(float* c, const uint32_t* a, const uint32_t* b) {
    asm volatile(
        "mma.sync.aligned.m16n8k16.row.col.f32.bf16.bf16.f32 "
        "{%0,%1,%2,%3}, {%4,%5,%6,%7}, {%8,%9}, {%0,%1,%2,%3};"
        : "+f"(c[0]), "+f"(c[1]), "+f"(c[2]), "+f"(c[3])
        : "r"(a[0]), "r"(a[1]), "r"(a[2]), "r"(a[3]), "r"(b[0]), "r"(b[1]));
}
__device__ __forceinline__ void ldm_a(uint32_t* r, uint32_t addr) {
    asm volatile("ldmatrix.sync.aligned.m8n8.x4.shared.b16 {%0,%1,%2,%3}, [%4];"
                 : "=r"(r[0]), "=r"(r[1]), "=r"(r[2]), "=r"(r[3]) : "r"(addr));
}
__device__ __forceinline__ void ldm_bt(uint32_t* r, uint32_t addr) {
    asm volatile("ldmatrix.sync.aligned.m8n8.x2.trans.shared.b16 {%0,%1}, [%2];"
                 : "=r"(r[0]), "=r"(r[1]) : "r"(addr));
}
__device__ __forceinline__ void cp16(uint32_t s, const void* g) {
    asm volatile("cp.async.cg.shared.global [%0], [%1], 16;" :: "r"(s), "l"(g));
}
__device__ __forceinline__ void cp_commit() { asm volatile("cp.async.commit_group;"); }
template <int N>
__device__ __forceinline__ void cp_wait() { asm volatile("cp.async.wait_group %0;" :: "n"(N)); }

__device__ __forceinline__ uint32_t bpack(__nv_bfloat16 a, __nv_bfloat16 b) {
    __nv_bfloat162 t = __halves2bfloat162(a, b);
    return *reinterpret_cast<uint32_t*>(&t);
}
__device__ __forceinline__ void split_pack4(float4 v, uint2& hi, uint2& lo) {
    __nv_bfloat16 h0 = __float2bfloat16(v.x), h1 = __float2bfloat16(v.y);
    __nv_bfloat16 h2 = __float2bfloat16(v.z), h3 = __float2bfloat16(v.w);
    hi.x = bpack(h0, h1); hi.y = bpack(h2, h3);
    lo.x = bpack(__float2bfloat16(v.x - __bfloat162float(h0)),
                 __float2bfloat16(v.y - __bfloat162float(h1)));
    lo.y = bpack(__float2bfloat16(v.z - __bfloat162float(h2)),
                 __float2bfloat16(v.w - __bfloat162float(h3)));
}

// stage one 32-row weight chunk (hi+lo planes, each contiguous 8704B) into smem buffer
__device__ __forceinline__ void stage_chunk(uint32_t dst, int wrow, int tid) {
    const char* sh = (const char*)(g_w_hi + (size_t)wrow * WPAD);
    const char* sl = (const char*)(g_w_lo + (size_t)wrow * WPAD);
    for (int i = tid; i < WCHUNK_B / 16; i += 256) cp16(dst + i * 16, sh + i * 16);
    for (int i = tid; i < WCHUNK_B / 16; i += 256) cp16(dst + WCHUNK_B + i * 16, sl + i * 16);
    cp_commit();
}

// GEMM: acc[4][4] = X[32 x KTOT] (split bf16 in smem) * W[KTOT x 128] (split bf16, pipelined).
// 8 warps = 2(M) x 4(N); warp tile 16x32; 3 mma per tile pair (hi*hi + hi*lo + lo*hi).
template <int KTOT>
__device__ __forceinline__ void gemm_layer(uint32_t sbase,
                                           uint32_t xh_off, uint32_t xl_off, int xsb,
                                           int wrow0, uint32_t wb_off,
                                           int tid, int lane, int wm, int wn,
                                           float acc[4][4]) {
#pragma unroll
    for (int nt = 0; nt < 4; nt++)
#pragma unroll
        for (int i = 0; i < 4; i++) acc[nt][i] = 0.f;

    const int nch = KTOT / 32;
    for (int ch = 0; ch < nch; ch++) {
        __syncthreads();   // prior reads of the buffer we are about to fill are done
        if (ch == 0)       stage_chunk(sbase + wb_off, wrow0, tid);
        if (ch + 1 < nch)  stage_chunk(sbase + wb_off + ((ch + 1) & 1) * WBUF_B,
                                       wrow0 + (ch + 1) * 32, tid);
        if (ch + 1 < nch)  cp_wait<1>(); else cp_wait<0>();
        __syncthreads();

        const uint32_t wbuf = sbase + wb_off + (ch & 1) * WBUF_B;
#pragma unroll
        for (int ks = 0; ks < 2; ks++) {
            const int kg = ch * 32 + ks * 16;
            uint32_t ah[4], al[4];
            uint32_t arow  = (uint32_t)(wm * 16 + (lane & 15));
            uint32_t acolb = (uint32_t)(kg + ((lane >> 4) << 3)) * 2;
            ldm_a(ah, sbase + xh_off + arow * xsb + acolb);
            ldm_a(al, sbase + xl_off + arow * xsb + acolb);
            uint32_t bh[4][2], bl[4][2];
            uint32_t brow = (uint32_t)(ks * 16 + (lane & 15)) * 272;
#pragma unroll
            for (int nt = 0; nt < 4; nt++) {
                uint32_t nb = (uint32_t)(wn * 32 + nt * 8) * 2;
                ldm_bt(bh[nt], wbuf + brow + nb);
                ldm_bt(bl[nt], wbuf + WCHUNK_B + brow + nb);
            }
#pragma unroll
            for (int nt = 0; nt < 4; nt++) {
                mma16816(acc[nt], ah, bh[nt]);
                mma16816(acc[nt], ah, bl[nt]);
                mma16816(acc[nt], al, bh[nt]);
            }
        }
    }
}

// epilogue: bias + relu, split to bf16 hi/lo h-planes (row stride 272B)
__device__ __forceinline__ void epi_relu_split(float acc[4][4], const float* __restrict__ bias,
                                               char* smem, uint32_t hh_off, uint32_t hl_off,
                                               int lane, int wm, int wn) {
#pragma unroll
    for (int nt = 0; nt < 4; nt++) {
        int n0 = wn * 32 + nt * 8 + (lane & 3) * 2;
        float2 bv = *(const float2*)(bias + n0);
        int r0 = wm * 16 + (lane >> 2);
        float v0 = fmaxf(acc[nt][0] + bv.x, 0.f);
        float v1 = fmaxf(acc[nt][1] + bv.y, 0.f);
        float v2 = fmaxf(acc[nt][2] + bv.x, 0.f);
        float v3 = fmaxf(acc[nt][3] + bv.y, 0.f);
        __nv_bfloat16 h0 = __float2bfloat16(v0), h1 = __float2bfloat16(v1);
        __nv_bfloat16 h2 = __float2bfloat16(v2), h3 = __float2bfloat16(v3);
        *(uint32_t*)(smem + hh_off + r0 * 272 + n0 * 2) = bpack(h0, h1);
        *(uint32_t*)(smem + hl_off + r0 * 272 + n0 * 2) =
            bpack(__float2bfloat16(v0 - __bfloat162float(h0)),
                  __float2bfloat16(v1 - __bfloat162float(h1)));
        *(uint32_t*)(smem + hh_off + (r0 + 8) * 272 + n0 * 2) = bpack(h2, h3);
        *(uint32_t*)(smem + hl_off + (r0 + 8) * 272 + n0 * 2) =
            bpack(__float2bfloat16(v2 - __bfloat162float(h2)),
                  __float2bfloat16(v3 - __bfloat162float(h3)));
    }
}

// epilogue layer3: bias only, fp32 to LN staging buffer (row stride 528B)
__device__ __forceinline__ void epi_f32(float acc[4][4], const float* __restrict__ bias,
                                        char* smem, uint32_t f_off, int lane, int wm, int wn) {
#pragma unroll
    for (int nt = 0; nt < 4; nt++) {
        int n0 = wn * 32 + nt * 8 + (lane & 3) * 2;
        float2 bv = *(const float2*)(bias + n0);
        int r0 = wm * 16 + (lane >> 2);
        *(float2*)(smem + f_off + r0 * 528 + n0 * 4) =
            make_float2(acc[nt][0] + bv.x, acc[nt][1] + bv.y);
        *(float2*)(smem + f_off + (r0 + 8) * 528 + n0 * 4) =
            make_float2(acc[nt][2] + bv.x, acc[nt][3] + bv.y);
    }
}

// ---------------- edge kernel (M-tile = 32 edges) ----------------
// smem: XH 0(25088) | XL 25088 | H1H 50176 H1L 58880 | H2H 25088(alias XL) H2L 33792 |
//       Wx2 67584..102400.  LN f32 staging (32*528=16896) aliases XH.
#define E_XH   0u
#define E_XL   25088u
#define E_H1H  50176u
#define E_H1L  58880u
#define E_H2H  25088u
#define E_H2L  33792u
#define E_WB   67584u
#define E_SMEM 102400

__global__ void __launch_bounds__(256, 2) edge_kernel(
    const float* __restrict__ nf, const float* __restrict__ ef,
    const int* __restrict__ senders, const int* __restrict__ receivers,
    const float* __restrict__ b1, const float* __restrict__ b2, const float* __restrict__ b3,
    const float* __restrict__ gamma, const float* __restrict__ beta,
    float* __restrict__ out_e) {
    extern __shared__ char smem[];
    const uint32_t sbase = (uint32_t)__cvta_generic_to_shared(smem);
    const int tid = threadIdx.x, lane = tid & 31, wid = tid >> 5;
    const int wm = wid >> 2, wn = wid & 3;
    const size_t base = (size_t)blockIdx.x * 32;

    // gather x = [v_i | v_j | ef] -> bf16 hi/lo planes, row stride 784B
    for (int task = wid; task < 96; task += 8) {
        int e = task & 31, seg = task >> 5;
        size_t ge = base + e;
        const float* src;
        if (seg == 0)      src = nf + (size_t)senders[ge] * D;
        else if (seg == 1) src = nf + (size_t)receivers[ge] * D;
        else               src = ef + ge * D;
        float4 v = *(const float4*)(src + lane * 4);
        uint2 hi, lo; split_pack4(v, hi, lo);
        uint32_t off = (uint32_t)e * 784 + (uint32_t)(seg * 128 + lane * 4) * 2;
        *(uint2*)(smem + E_XH + off) = hi;
        *(uint2*)(smem + E_XL + off) = lo;
    }

    float acc[4][4];
    gemm_layer<384>(sbase, E_XH, E_XL, 784, 0,   E_WB, tid, lane, wm, wn, acc);
    epi_relu_split(acc, b1, smem, E_H1H, E_H1L, lane, wm, wn);
    gemm_layer<128>(sbase, E_H1H, E_H1L, 272, 384, E_WB, tid, lane, wm, wn, acc);
    epi_relu_split(acc, b2, smem, E_H2H, E_H2L, lane, wm, wn);
    gemm_layer<128>(sbase, E_H2H, E_H2L, 272, 512, E_WB, tid, lane, wm, wn, acc);
    epi_f32(acc, b3, smem, 0u, lane, wm, wn);   // aliases dead x region
    __syncthreads();

    // LN + segment-sum scatter + residual (16 threads per row, 2 rows per group)
    const int ccg = tid & 15, ecg = tid >> 4;
    float4 g0 = *(const float4*)(gamma + ccg * 8), g1 = *(const float4*)(gamma + ccg * 8 + 4);
    float4 t0 = *(const float4*)(beta + ccg * 8),  t1 = *(const float4*)(beta + ccg * 8 + 4);
    float gv[8] = {g0.x, g0.y, g0.z, g0.w, g1.x, g1.y, g1.z, g1.w};
    float bv[8] = {t0.x, t0.y, t0.z, t0.w, t1.x, t1.y, t1.z, t1.w};
#pragma unroll
    for (int ei = 0; ei < 2; ei++) {
        int el = ecg * 2 + ei;
        float4 p0 = *(float4*)(smem + (uint32_t)el * 528 + ccg * 32);
        float4 p1 = *(float4*)(smem + (uint32_t)el * 528 + ccg * 32 + 16);
        float v[8] = {p0.x, p0.y, p0.z, p0.w, p1.x, p1.y, p1.z, p1.w};
        float s = 0.f, s2 = 0.f;
#pragma unroll
        for (int c = 0; c < 8; c++) { s += v[c]; s2 += v[c] * v[c]; }
#pragma unroll
        for (int m = 8; m >= 1; m >>= 1) {
            s  += __shfl_xor_sync(0xffffffffu, s, m);
            s2 += __shfl_xor_sync(0xffffffffu, s2, m);
        }
        float mu = s * (1.f / D);
        float var = s2 * (1.f / D) - mu * mu;
        float rstd = rsqrtf(fmaxf(var, 0.f) + 1e-5f);
        size_t ge = base + el;
        int r = receivers[ge];
        float nrm[8];
#pragma unroll
        for (int c = 0; c < 8; c++) nrm[c] = (v[c] - mu) * rstd * gv[c] + bv[c];
        float* ap = g_agg + (size_t)r * D + ccg * 8;
        asm volatile("red.global.add.v4.f32 [%0], {%1,%2,%3,%4};" ::
                     "l"(ap), "f"(nrm[0]), "f"(nrm[1]), "f"(nrm[2]), "f"(nrm[3]) : "memory");
        asm volatile("red.global.add.v4.f32 [%0], {%1,%2,%3,%4};" ::
                     "l"(ap + 4), "f"(nrm[4]), "f"(nrm[5]), "f"(nrm[6]), "f"(nrm[7]) : "memory");
        const float4 e0 = *(const float4*)(ef + ge * D + ccg * 8);
        const float4 e1 = *(const float4*)(ef + ge * D + ccg * 8 + 4);
        float* op = out_e + ge * D + ccg * 8;
        *(float4*)op       = make_float4(nrm[0] + e0.x, nrm[1] + e0.y, nrm[2] + e0.z, nrm[3] + e0.w);
        *(float4*)(op + 4) = make_float4(nrm[4] + e1.x, nrm[5] + e1.y, nrm[6] + e1.z, nrm[7] + e1.w);
    }
}

// ---------------- node kernel (M-tile = 32 nodes) ----------------
// smem: XH 0(16896) | XL 16896 | H1H 33792 H1L 42496 | H2H 16896(alias XL) H2L 25600 |
//       Wx2 51200..86016.  LN staging aliases XH.
#define N_XH   0u
#define N_XL   16896u
#define N_H1H  33792u
#define N_H1L  42496u
#define N_H2H  16896u
#define N_H2L  25600u
#define N_WB   51200u
#define N_SMEM 86016

__global__ void __launch_bounds__(256, 2) node_kernel(
    const float* __restrict__ nf,
    const float* __restrict__ b1, const float* __restrict__ b2, const float* __restrict__ b3,
    const float* __restrict__ gamma, const float* __restrict__ beta,
    float* __restrict__ out_n) {
    extern __shared__ char smem[];
    const uint32_t sbase = (uint32_t)__cvta_generic_to_shared(smem);
    const int tid = threadIdx.x, lane = tid & 31, wid = tid >> 5;
    const int wm = wid >> 2, wn = wid & 3;
    const size_t base = (size_t)blockIdx.x * 32;

    for (int task = wid; task < 64; task += 8) {
        int e = task & 31, seg = task >> 5;
        size_t ge = base + e;
        float4 v = make_float4(0.f, 0.f, 0.f, 0.f);
        if (ge < NN) {
            const float* src = (seg == 0) ? (nf + ge * D) : (g_agg + ge * D);
            v = *(const float4*)(src + lane * 4);
        }
        uint2 hi, lo; split_pack4(v, hi, lo);
        uint32_t off = (uint32_t)e * 528 + (uint32_t)(seg * 128 + lane * 4) * 2;
        *(uint2*)(smem + N_XH + off) = hi;
        *(uint2*)(smem + N_XL + off) = lo;
    }

    float acc[4][4];
    gemm_layer<256>(sbase, N_XH, N_XL, 528, 640,  N_WB, tid, lane, wm, wn, acc);
    epi_relu_split(acc, b1, smem, N_H1H, N_H1L, lane, wm, wn);
    gemm_layer<128>(sbase, N_H1H, N_H1L, 272, 896, N_WB, tid, lane, wm, wn, acc);
    epi_relu_split(acc, b2, smem, N_H2H, N_H2L, lane, wm, wn);
    gemm_layer<128>(sbase, N_H2H, N_H2L, 272, 1024, N_WB, tid, lane, wm, wn, acc);
    epi_f32(acc, b3, smem, 0u, lane, wm, wn);
    __syncthreads();

    const int ccg = tid & 15, ecg = tid >> 4;
    float4 g0 = *(const float4*)(gamma + ccg * 8), g1 = *(const float4*)(gamma + ccg * 8 + 4);
    float4 t0 = *(const float4*)(beta + ccg * 8),  t1 = *(const float4*)(beta + ccg * 8 + 4);
    float gv[8] = {g0.x, g0.y, g0.z, g0.w, g1.x, g1.y, g1.z, g1.w};
    float bv[8] = {t0.x, t0.y, t0.z, t0.w, t1.x, t1.y, t1.z, t1.w};
#pragma unroll
    for (int ei = 0; ei < 2; ei++) {
        int el = ecg * 2 + ei;
        float4 p0 = *(float4*)(smem + (uint32_t)el * 528 + ccg * 32);
        float4 p1 = *(float4*)(smem + (uint32_t)el * 528 + ccg * 32 + 16);
        float v[8] = {p0.x, p0.y, p0.z, p0.w, p1.x, p1.y, p1.z, p1.w};
        float s = 0.f, s2 = 0.f;
#pragma unroll
        for (int c = 0; c < 8; c++) { s += v[c]; s2 += v[c] * v[c]; }
#pragma unroll
        for (int m = 8; m >= 1; m >>= 1) {
            s  += __shfl_xor_sync(0xffffffffu, s, m);
            s2 += __shfl_xor_sync(0xffffffffu, s2, m);
        }
        float mu = s * (1.f / D);
        float var = s2 * (1.f / D) - mu * mu;
        float rstd = rsqrtf(fmaxf(var, 0.f) + 1e-5f);
        size_t ge = base + el;
        if (ge < NN) {
            const float4 n0v = *(const float4*)(nf + ge * D + ccg * 8);
            const float4 n1v = *(const float4*)(nf + ge * D + ccg * 8 + 4);
            float nrm[8];
#pragma unroll
            for (int c = 0; c < 8; c++) nrm[c] = (v[c] - mu) * rstd * gv[c] + bv[c];
            float* op = out_n + ge * D + ccg * 8;
            *(float4*)op       = make_float4(nrm[0] + n0v.x, nrm[1] + n0v.y, nrm[2] + n0v.z, nrm[3] + n0v.w);
            *(float4*)(op + 4) = make_float4(nrm[4] + n1v.x, nrm[5] + n1v.y, nrm[6] + n1v.z, nrm[7] + n1v.w);
        }
    }
}

extern "C" void kernel_launch(void* const* d_in, const int* in_sizes, int n_in,
                              void* d_out, int out_size) {
    const float* nf  = (const float*)d_in[0];
    const float* ef  = (const float*)d_in[1];
    const int*   snd = (const int*)d_in[2];
    const int*   rcv = (const int*)d_in[3];
    const float* ew1 = (const float*)d_in[4];
    const float* eb1 = (const float*)d_in[5];
    const float* ew2 = (const float*)d_in[6];
    const float* eb2 = (const float*)d_in[7];
    const float* ew3 = (const float*)d_in[8];
    const float* eb3 = (const float*)d_in[9];
    const float* eg  = (const float*)d_in[10];
    const float* ebt = (const float*)d_in[11];
    const float* nw1 = (const float*)d_in[12];
    const float* nb1 = (const float*)d_in[13];
    const float* nw2 = (const float*)d_in[14];
    const float* nb2 = (const float*)d_in[15];
    const float* nw3 = (const float*)d_in[16];
    const float* nb3 = (const float*)d_in[17];
    const float* ng  = (const float*)d_in[18];
    const float* nbt = (const float*)d_in[19];

    float* out_n = (float*)d_out;
    float* out_e = out_n + (size_t)NN * D;

    cudaFuncSetAttribute(edge_kernel, cudaFuncAttributeMaxDynamicSharedMemorySize, E_SMEM);
    cudaFuncSetAttribute(node_kernel, cudaFuncAttributeMaxDynamicSharedMemorySize, N_SMEM);

    prep_weights<<<612, 256>>>(ew1, ew2, ew3, nw1, nw2, nw3);
    zero_agg_kernel<<<NN * D / 4 / 256, 256>>>();
    edge_kernel<<<NE / 32, 256, E_SMEM>>>(nf, ef, snd, rcv, eb1, eb2, eb3, eg, ebt, out_e);
    node_kernel<<<(NN + 31) / 32, 256, N_SMEM>>>(nf, nb1, nb2, nb3, ng, nbt, out_n);
}

// round 4
// speedup vs baseline: 3.5310x; 1.0004x over previous
#include <cuda_runtime.h>
#include <cuda_bf16.h>
#include <cstdint>

#define NN 100000
#define NE 600000
#define D  128
#define WPAD 136            // padded weight row width (272B rows: %128 == 16)
#define WCHUNK_B 8704       // 32 rows * 272B, per plane
#define WBUF_B   17408      // hi + lo planes per buffer

// ---------------- global scratch (no cudaMalloc allowed) ----------------
__device__ float g_agg[(size_t)NN * D];
// pre-split weights, bf16 hi/lo planes, rows stacked:
// [0,384) ew1 | [384,512) ew2 | [512,640) ew3 | [640,896) nw1[0:256] | [896,1024) nw2 | [1024,1152) nw3
__device__ __nv_bfloat16 g_w_hi[1152 * WPAD];
__device__ __nv_bfloat16 g_w_lo[1152 * WPAD];

__global__ void zero_agg_kernel() {
    size_t i = (size_t)blockIdx.x * blockDim.x + threadIdx.x;
    ((float4*)g_agg)[i] = make_float4(0.f, 0.f, 0.f, 0.f);
}

__global__ void prep_weights(const float* __restrict__ ew1, const float* __restrict__ ew2,
                             const float* __restrict__ ew3, const float* __restrict__ nw1,
                             const float* __restrict__ nw2, const float* __restrict__ nw3) {
    int idx = blockIdx.x * 256 + threadIdx.x;
    if (idx >= 1152 * WPAD) return;
    int r = idx / WPAD, c = idx % WPAD;
    float v = 0.f;
    if (c < 128) {
        if (r < 384)       v = ew1[r * 128 + c];
        else if (r < 512)  v = ew2[(r - 384) * 128 + c];
        else if (r < 640)  v = ew3[(r - 512) * 128 + c];
        else if (r < 896)  v = nw1[(r - 640) * 128 + c];
        else if (r < 1024) v = nw2[(r - 896) * 128 + c];
        else               v = nw3[(r - 1024) * 128 + c];
    }
    __nv_bfloat16 h = __float2bfloat16(v);
    g_w_hi[idx] = h;
    g_w_lo[idx] = __float2bfloat16(v - __bfloat162float(h));
}

// ---------------- mma / ldmatrix / cp.async helpers ----------------
__device__ __forceinline__ void mma16816(float* c, const uint32_t* a, const uint32_t* b) {
    asm volatile(
        "mma.sync.aligned.m16n8k16.row.col.f32.bf16.bf16.f32 "
        "{%0,%1,%2,%3}, {%4,%5,%6,%7}, {%8,%9}, {%0,%1,%2,%3};"
        : "+f"(c[0]), "+f"(c[1]), "+f"(c[2]), "+f"(c[3])
        : "r"(a[0]), "r"(a[1]), "r"(a[2]), "r"(a[3]), "r"(b[0]), "r"(b[1]));
}
__device__ __forceinline__ void ldm_a(uint32_t* r, uint32_t addr) {
    asm volatile("ldmatrix.sync.aligned.m8n8.x4.shared.b16 {%0,%1,%2,%3}, [%4];"
                 : "=r"(r[0]), "=r"(r[1]), "=r"(r[2]), "=r"(r[3]) : "r"(addr));
}
__device__ __forceinline__ void ldm_bt(uint32_t* r, uint32_t addr) {
    asm volatile("ldmatrix.sync.aligned.m8n8.x2.trans.shared.b16 {%0,%1}, [%2];"
                 : "=r"(r[0]), "=r"(r[1]) : "r"(addr));
}
__device__ __forceinline__ void cp16(uint32_t s, const void* g) {
    asm volatile("cp.async.cg.shared.global [%0], [%1], 16;" :: "r"(s), "l"(g));
}
__device__ __forceinline__ void cp_commit() { asm volatile("cp.async.commit_group;"); }
template <int N>
__device__ __forceinline__ void cp_wait() { asm volatile("cp.async.wait_group %0;" :: "n"(N)); }

__device__ __forceinline__ uint32_t bpack(__nv_bfloat16 a, __nv_bfloat16 b) {
    __nv_bfloat162 t = __halves2bfloat162(a, b);
    return *reinterpret_cast<uint32_t*>(&t);
}
__device__ __forceinline__ void split_pack4(float4 v, uint2& hi, uint2& lo) {
    __nv_bfloat16 h0 = __float2bfloat16(v.x), h1 = __float2bfloat16(v.y);
    __nv_bfloat16 h2 = __float2bfloat16(v.z), h3 = __float2bfloat16(v.w);
    hi.x = bpack(h0, h1); hi.y = bpack(h2, h3);
    lo.x = bpack(__float2bfloat16(v.x - __bfloat162float(h0)),
                 __float2bfloat16(v.y - __bfloat162float(h1)));
    lo.y = bpack(__float2bfloat16(v.z - __bfloat162float(h2)),
                 __float2bfloat16(v.w - __bfloat162float(h3)));
}

// stage one 32-row weight chunk (hi+lo planes, each contiguous 8704B) into smem buffer
__device__ __forceinline__ void stage_chunk(uint32_t dst, int wrow, int tid) {
    const char* sh = (const char*)(g_w_hi + (size_t)wrow * WPAD);
    const char* sl = (const char*)(g_w_lo + (size_t)wrow * WPAD);
    for (int i = tid; i < WCHUNK_B / 16; i += 256) cp16(dst + i * 16, sh + i * 16);
    for (int i = tid; i < WCHUNK_B / 16; i += 256) cp16(dst + WCHUNK_B + i * 16, sl + i * 16);
    cp_commit();
}

// GEMM: acc[4][4] = X[32 x KTOT] (split bf16 in smem) * W[KTOT x 128] (split bf16, pipelined).
// 8 warps = 2(M) x 4(N); warp tile 16x32; 3 mma per tile pair (hi*hi + hi*lo + lo*hi).
template <int KTOT>
__device__ __forceinline__ void gemm_layer(uint32_t sbase,
                                           uint32_t xh_off, uint32_t xl_off, int xsb,
                                           int wrow0, uint32_t wb_off,
                                           int tid, int lane, int wm, int wn,
                                           float acc[4][4]) {
#pragma unroll
    for (int nt = 0; nt < 4; nt++)
#pragma unroll
        for (int i = 0; i < 4; i++) acc[nt][i] = 0.f;

    const int nch = KTOT / 32;
    for (int ch = 0; ch < nch; ch++) {
        __syncthreads();   // prior reads of the buffer we are about to fill are done
        if (ch == 0)       stage_chunk(sbase + wb_off, wrow0, tid);
        if (ch + 1 < nch)  stage_chunk(sbase + wb_off + ((ch + 1) & 1) * WBUF_B,
                                       wrow0 + (ch + 1) * 32, tid);
        if (ch + 1 < nch)  cp_wait<1>(); else cp_wait<0>();
        __syncthreads();

        const uint32_t wbuf = sbase + wb_off + (ch & 1) * WBUF_B;
#pragma unroll
        for (int ks = 0; ks < 2; ks++) {
            const int kg = ch * 32 + ks * 16;
            uint32_t ah[4], al[4];
            uint32_t arow  = (uint32_t)(wm * 16 + (lane & 15));
            uint32_t acolb = (uint32_t)(kg + ((lane >> 4) << 3)) * 2;
            ldm_a(ah, sbase + xh_off + arow * xsb + acolb);
            ldm_a(al, sbase + xl_off + arow * xsb + acolb);
            uint32_t bh[4][2], bl[4][2];
            uint32_t brow = (uint32_t)(ks * 16 + (lane & 15)) * 272;
#pragma unroll
            for (int nt = 0; nt < 4; nt++) {
                uint32_t nb = (uint32_t)(wn * 32 + nt * 8) * 2;
                ldm_bt(bh[nt], wbuf + brow + nb);
                ldm_bt(bl[nt], wbuf + WCHUNK_B + brow + nb);
            }
#pragma unroll
            for (int nt = 0; nt < 4; nt++) {
                mma16816(acc[nt], ah, bh[nt]);
                mma16816(acc[nt], ah, bl[nt]);
                mma16816(acc[nt], al, bh[nt]);
            }
        }
    }
}

// epilogue: bias + relu, split to bf16 hi/lo h-planes (row stride 272B)
__device__ __forceinline__ void epi_relu_split(float acc[4][4], const float* __restrict__ bias,
                                               char* smem, uint32_t hh_off, uint32_t hl_off,
                                               int lane, int wm, int wn) {
#pragma unroll
    for (int nt = 0; nt < 4; nt++) {
        int n0 = wn * 32 + nt * 8 + (lane & 3) * 2;
        float2 bv = *(const float2*)(bias + n0);
        int r0 = wm * 16 + (lane >> 2);
        float v0 = fmaxf(acc[nt][0] + bv.x, 0.f);
        float v1 = fmaxf(acc[nt][1] + bv.y, 0.f);
        float v2 = fmaxf(acc[nt][2] + bv.x, 0.f);
        float v3 = fmaxf(acc[nt][3] + bv.y, 0.f);
        __nv_bfloat16 h0 = __float2bfloat16(v0), h1 = __float2bfloat16(v1);
        __nv_bfloat16 h2 = __float2bfloat16(v2), h3 = __float2bfloat16(v3);
        *(uint32_t*)(smem + hh_off + r0 * 272 + n0 * 2) = bpack(h0, h1);
        *(uint32_t*)(smem + hl_off + r0 * 272 + n0 * 2) =
            bpack(__float2bfloat16(v0 - __bfloat162float(h0)),
                  __float2bfloat16(v1 - __bfloat162float(h1)));
        *(uint32_t*)(smem + hh_off + (r0 + 8) * 272 + n0 * 2) = bpack(h2, h3);
        *(uint32_t*)(smem + hl_off + (r0 + 8) * 272 + n0 * 2) =
            bpack(__float2bfloat16(v2 - __bfloat162float(h2)),
                  __float2bfloat16(v3 - __bfloat162float(h3)));
    }
}

// epilogue layer3: bias only, fp32 to LN staging buffer (row stride 528B)
__device__ __forceinline__ void epi_f32(float acc[4][4], const float* __restrict__ bias,
                                        char* smem, uint32_t f_off, int lane, int wm, int wn) {
#pragma unroll
    for (int nt = 0; nt < 4; nt++) {
        int n0 = wn * 32 + nt * 8 + (lane & 3) * 2;
        float2 bv = *(const float2*)(bias + n0);
        int r0 = wm * 16 + (lane >> 2);
        *(float2*)(smem + f_off + r0 * 528 + n0 * 4) =
            make_float2(acc[nt][0] + bv.x, acc[nt][1] + bv.y);
        *(float2*)(smem + f_off + (r0 + 8) * 528 + n0 * 4) =
            make_float2(acc[nt][2] + bv.x, acc[nt][3] + bv.y);
    }
}

// ---------------- edge kernel (M-tile = 32 edges) ----------------
// smem: XH 0(25088) | XL 25088 | H1H 50176 H1L 58880 | H2H 25088(alias XL) H2L 33792 |
//       Wx2 67584..102400.  LN f32 staging (32*528=16896) aliases XH.
#define E_XH   0u
#define E_XL   25088u
#define E_H1H  50176u
#define E_H1L  58880u
#define E_H2H  25088u
#define E_H2L  33792u
#define E_WB   67584u
#define E_SMEM 102400

__global__ void __launch_bounds__(256, 2) edge_kernel(
    const float* __restrict__ nf, const float* __restrict__ ef,
    const int* __restrict__ senders, const int* __restrict__ receivers,
    const float* __restrict__ b1, const float* __restrict__ b2, const float* __restrict__ b3,
    const float* __restrict__ gamma, const float* __restrict__ beta,
    float* __restrict__ out_e) {
    extern __shared__ char smem[];
    const uint32_t sbase = (uint32_t)__cvta_generic_to_shared(smem);
    const int tid = threadIdx.x, lane = tid & 31, wid = tid >> 5;
    const int wm = wid >> 2, wn = wid & 3;
    const size_t base = (size_t)blockIdx.x * 32;

    // gather x = [v_i | v_j | ef] -> bf16 hi/lo planes, row stride 784B
    for (int task = wid; task < 96; task += 8) {
        int e = task & 31, seg = task >> 5;
        size_t ge = base + e;
        const float* src;
        if (seg == 0)      src = nf + (size_t)senders[ge] * D;
        else if (seg == 1) src = nf + (size_t)receivers[ge] * D;
        else               src = ef + ge * D;
        float4 v = *(const float4*)(src + lane * 4);
        uint2 hi, lo; split_pack4(v, hi, lo);
        uint32_t off = (uint32_t)e * 784 + (uint32_t)(seg * 128 + lane * 4) * 2;
        *(uint2*)(smem + E_XH + off) = hi;
        *(uint2*)(smem + E_XL + off) = lo;
    }

    float acc[4][4];
    gemm_layer<384>(sbase, E_XH, E_XL, 784, 0,   E_WB, tid, lane, wm, wn, acc);
    epi_relu_split(acc, b1, smem, E_H1H, E_H1L, lane, wm, wn);
    gemm_layer<128>(sbase, E_H1H, E_H1L, 272, 384, E_WB, tid, lane, wm, wn, acc);
    epi_relu_split(acc, b2, smem, E_H2H, E_H2L, lane, wm, wn);
    gemm_layer<128>(sbase, E_H2H, E_H2L, 272, 512, E_WB, tid, lane, wm, wn, acc);
    epi_f32(acc, b3, smem, 0u, lane, wm, wn);   // aliases dead x region
    __syncthreads();

    // LN + segment-sum scatter + residual (16 threads per row, 2 rows per group)
    const int ccg = tid & 15, ecg = tid >> 4;
    float4 g0 = *(const float4*)(gamma + ccg * 8), g1 = *(const float4*)(gamma + ccg * 8 + 4);
    float4 t0 = *(const float4*)(beta + ccg * 8),  t1 = *(const float4*)(beta + ccg * 8 + 4);
    float gv[8] = {g0.x, g0.y, g0.z, g0.w, g1.x, g1.y, g1.z, g1.w};
    float bv[8] = {t0.x, t0.y, t0.z, t0.w, t1.x, t1.y, t1.z, t1.w};
#pragma unroll
    for (int ei = 0; ei < 2; ei++) {
        int el = ecg * 2 + ei;
        float4 p0 = *(float4*)(smem + (uint32_t)el * 528 + ccg * 32);
        float4 p1 = *(float4*)(smem + (uint32_t)el * 528 + ccg * 32 + 16);
        float v[8] = {p0.x, p0.y, p0.z, p0.w, p1.x, p1.y, p1.z, p1.w};
        float s = 0.f, s2 = 0.f;
#pragma unroll
        for (int c = 0; c < 8; c++) { s += v[c]; s2 += v[c] * v[c]; }
#pragma unroll
        for (int m = 8; m >= 1; m >>= 1) {
            s  += __shfl_xor_sync(0xffffffffu, s, m);
            s2 += __shfl_xor_sync(0xffffffffu, s2, m);
        }
        float mu = s * (1.f / D);
        float var = s2 * (1.f / D) - mu * mu;
        float rstd = rsqrtf(fmaxf(var, 0.f) + 1e-5f);
        size_t ge = base + el;
        int r = receivers[ge];
        float nrm[8];
#pragma unroll
        for (int c = 0; c < 8; c++) nrm[c] = (v[c] - mu) * rstd * gv[c] + bv[c];
        float* ap = g_agg + (size_t)r * D + ccg * 8;
        asm volatile("red.global.add.v4.f32 [%0], {%1,%2,%3,%4};" ::
                     "l"(ap), "f"(nrm[0]), "f"(nrm[1]), "f"(nrm[2]), "f"(nrm[3]) : "memory");
        asm volatile("red.global.add.v4.f32 [%0], {%1,%2,%3,%4};" ::
                     "l"(ap + 4), "f"(nrm[4]), "f"(nrm[5]), "f"(nrm[6]), "f"(nrm[7]) : "memory");
        const float4 e0 = *(const float4*)(ef + ge * D + ccg * 8);
        const float4 e1 = *(const float4*)(ef + ge * D + ccg * 8 + 4);
        float* op = out_e + ge * D + ccg * 8;
        *(float4*)op       = make_float4(nrm[0] + e0.x, nrm[1] + e0.y, nrm[2] + e0.z, nrm[3] + e0.w);
        *(float4*)(op + 4) = make_float4(nrm[4] + e1.x, nrm[5] + e1.y, nrm[6] + e1.z, nrm[7] + e1.w);
    }
}

// ---------------- node kernel (M-tile = 32 nodes) ----------------
// smem: XH 0(16896) | XL 16896 | H1H 33792 H1L 42496 | H2H 16896(alias XL) H2L 25600 |
//       Wx2 51200..86016.  LN staging aliases XH.
#define N_XH   0u
#define N_XL   16896u
#define N_H1H  33792u
#define N_H1L  42496u
#define N_H2H  16896u
#define N_H2L  25600u
#define N_WB   51200u
#define N_SMEM 86016

__global__ void __launch_bounds__(256, 2) node_kernel(
    const float* __restrict__ nf,
    const float* __restrict__ b1, const float* __restrict__ b2, const float* __restrict__ b3,
    const float* __restrict__ gamma, const float* __restrict__ beta,
    float* __restrict__ out_n) {
    extern __shared__ char smem[];
    const uint32_t sbase = (uint32_t)__cvta_generic_to_shared(smem);
    const int tid = threadIdx.x, lane = tid & 31, wid = tid >> 5;
    const int wm = wid >> 2, wn = wid & 3;
    const size_t base = (size_t)blockIdx.x * 32;

    for (int task = wid; task < 64; task += 8) {
        int e = task & 31, seg = task >> 5;
        size_t ge = base + e;
        float4 v = make_float4(0.f, 0.f, 0.f, 0.f);
        if (ge < NN) {
            const float* src = (seg == 0) ? (nf + ge * D) : (g_agg + ge * D);
            v = *(const float4*)(src + lane * 4);
        }
        uint2 hi, lo; split_pack4(v, hi, lo);
        uint32_t off = (uint32_t)e * 528 + (uint32_t)(seg * 128 + lane * 4) * 2;
        *(uint2*)(smem + N_XH + off) = hi;
        *(uint2*)(smem + N_XL + off) = lo;
    }

    float acc[4][4];
    gemm_layer<256>(sbase, N_XH, N_XL, 528, 640,  N_WB, tid, lane, wm, wn, acc);
    epi_relu_split(acc, b1, smem, N_H1H, N_H1L, lane, wm, wn);
    gemm_layer<128>(sbase, N_H1H, N_H1L, 272, 896, N_WB, tid, lane, wm, wn, acc);
    epi_relu_split(acc, b2, smem, N_H2H, N_H2L, lane, wm, wn);
    gemm_layer<128>(sbase, N_H2H, N_H2L, 272, 1024, N_WB, tid, lane, wm, wn, acc);
    epi_f32(acc, b3, smem, 0u, lane, wm, wn);
    __syncthreads();

    const int ccg = tid & 15, ecg = tid >> 4;
    float4 g0 = *(const float4*)(gamma + ccg * 8), g1 = *(const float4*)(gamma + ccg * 8 + 4);
    float4 t0 = *(const float4*)(beta + ccg * 8),  t1 = *(const float4*)(beta + ccg * 8 + 4);
    float gv[8] = {g0.x, g0.y, g0.z, g0.w, g1.x, g1.y, g1.z, g1.w};
    float bv[8] = {t0.x, t0.y, t0.z, t0.w, t1.x, t1.y, t1.z, t1.w};
#pragma unroll
    for (int ei = 0; ei < 2; ei++) {
        int el = ecg * 2 + ei;
        float4 p0 = *(float4*)(smem + (uint32_t)el * 528 + ccg * 32);
        float4 p1 = *(float4*)(smem + (uint32_t)el * 528 + ccg * 32 + 16);
        float v[8] = {p0.x, p0.y, p0.z, p0.w, p1.x, p1.y, p1.z, p1.w};
        float s = 0.f, s2 = 0.f;
#pragma unroll
        for (int c = 0; c < 8; c++) { s += v[c]; s2 += v[c] * v[c]; }
#pragma unroll
        for (int m = 8; m >= 1; m >>= 1) {
            s  += __shfl_xor_sync(0xffffffffu, s, m);
            s2 += __shfl_xor_sync(0xffffffffu, s2, m);
        }
        float mu = s * (1.f / D);
        float var = s2 * (1.f / D) - mu * mu;
        float rstd = rsqrtf(fmaxf(var, 0.f) + 1e-5f);
        size_t ge = base + el;
        if (ge < NN) {
            const float4 n0v = *(const float4*)(nf + ge * D + ccg * 8);
            const float4 n1v = *(const float4*)(nf + ge * D + ccg * 8 + 4);
            float nrm[8];
#pragma unroll
            for (int c = 0; c < 8; c++) nrm[c] = (v[c] - mu) * rstd * gv[c] + bv[c];
            float* op = out_n + ge * D + ccg * 8;
            *(float4*)op       = make_float4(nrm[0] + n0v.x, nrm[1] + n0v.y, nrm[2] + n0v.z, nrm[3] + n0v.w);
            *(float4*)(op + 4) = make_float4(nrm[4] + n1v.x, nrm[5] + n1v.y, nrm[6] + n1v.z, nrm[7] + n1v.w);
        }
    }
}

extern "C" void kernel_launch(void* const* d_in, const int* in_sizes, int n_in,
                              void* d_out, int out_size) {
    const float* nf  = (const float*)d_in[0];
    const float* ef  = (const float*)d_in[1];
    const int*   snd = (const int*)d_in[2];
    const int*   rcv = (const int*)d_in[3];
    const float* ew1 = (const float*)d_in[4];
    const float* eb1 = (const float*)d_in[5];
    const float* ew2 = (const float*)d_in[6];
    const float* eb2 = (const float*)d_in[7];
    const float* ew3 = (const float*)d_in[8];
    const float* eb3 = (const float*)d_in[9];
    const float* eg  = (const float*)d_in[10];
    const float* ebt = (const float*)d_in[11];
    const float* nw1 = (const float*)d_in[12];
    const float* nb1 = (const float*)d_in[13];
    const float* nw2 = (const float*)d_in[14];
    const float* nb2 = (const float*)d_in[15];
    const float* nw3 = (const float*)d_in[16];
    const float* nb3 = (const float*)d_in[17];
    const float* ng  = (const float*)d_in[18];
    const float* nbt = (const float*)d_in[19];

    float* out_n = (float*)d_out;
    float* out_e = out_n + (size_t)NN * D;

    cudaFuncSetAttribute(edge_kernel, cudaFuncAttributeMaxDynamicSharedMemorySize, E_SMEM);
    cudaFuncSetAttribute(node_kernel, cudaFuncAttributeMaxDynamicSharedMemorySize, N_SMEM);

    prep_weights<<<612, 256>>>(ew1, ew2, ew3, nw1, nw2, nw3);
    zero_agg_kernel<<<NN * D / 4 / 256, 256>>>();
    edge_kernel<<<NE / 32, 256, E_SMEM>>>(nf, ef, snd, rcv, eb1, eb2, eb3, eg, ebt, out_e);
    node_kernel<<<(NN + 31) / 32, 256, N_SMEM>>>(nf, nb1, nb2, nb3, ng, nbt, out_n);
}

// round 6
// speedup vs baseline: 4.7211x; 1.3371x over previous
#include <cuda_runtime.h>
#include <cuda_bf16.h>
#include <cstdint>

#define NN 100000
#define NE 600000
#define D  128
#define WPAD 136            // weight row width (272B rows)

// smem layout (bytes): two stream buffers [X(10240: hi 5120|lo 5120) + W(17408: hi 8704|lo 8704)]
// then h (hi 17408 | lo 17408). LN staging (64*528=33792) aliases stream buffers.
#define XSTR   80u
#define BUFSZ  27648u
#define XOFF(b) ((uint32_t)(b) * BUFSZ)
#define WOFF(b) ((uint32_t)(b) * BUFSZ + 10240u)
#define SM_H    55296u
#define SM_STG  0u
#define SM_IDXS 90112u
#define SM_IDXR 90368u
#define SMEM_TOTAL 90624

__device__ float g_agg[(size_t)NN * D];
// stacked pre-split weights (rows x 272B): [0,384) ew1 | [384,512) ew2 | [512,640) ew3 |
// [640,896) nw1[0:256] | [896,1024) nw2 | [1024,1152) nw3
__device__ __nv_bfloat16 g_w_hi[1152 * WPAD];
__device__ __nv_bfloat16 g_w_lo[1152 * WPAD];

__global__ void zero_agg_kernel() {
    size_t i = (size_t)blockIdx.x * blockDim.x + threadIdx.x;
    ((float4*)g_agg)[i] = make_float4(0.f, 0.f, 0.f, 0.f);
}

__global__ void prep_weights(const float* __restrict__ ew1, const float* __restrict__ ew2,
                             const float* __restrict__ ew3, const float* __restrict__ nw1,
                             const float* __restrict__ nw2, const float* __restrict__ nw3) {
    int idx = blockIdx.x * 256 + threadIdx.x;
    if (idx >= 1152 * WPAD) return;
    int r = idx / WPAD, c = idx % WPAD;
    float v = 0.f;
    if (c < 128) {
        if (r < 384)       v = ew1[r * 128 + c];
        else if (r < 512)  v = ew2[(r - 384) * 128 + c];
        else if (r < 640)  v = ew3[(r - 512) * 128 + c];
        else if (r < 896)  v = nw1[(r - 640) * 128 + c];
        else if (r < 1024) v = nw2[(r - 896) * 128 + c];
        else               v = nw3[(r - 1024) * 128 + c];
    }
    __nv_bfloat16 h = __float2bfloat16(v);
    g_w_hi[idx] = h;
    g_w_lo[idx] = __float2bfloat16(v - __bfloat162float(h));
}

// ---------------- helpers ----------------
__device__ __forceinline__ void mma16816(float* c, const uint32_t* a, const uint32_t* b) {
    asm volatile(
        "mma.sync.aligned.m16n8k16.row.col.f32.bf16.bf16.f32 "
        "{%0,%1,%2,%3}, {%4,%5,%6,%7}, {%8,%9}, {%0,%1,%2,%3};"
        : "+f"(c[0]), "+f"(c[1]), "+f"(c[2]), "+f"(c[3])
        : "r"(a[0]), "r"(a[1]), "r"(a[2]), "r"(a[3]), "r"(b[0]), "r"(b[1]));
}
__device__ __forceinline__ void ldm_a(uint32_t* r, uint32_t addr) {
    asm volatile("ldmatrix.sync.aligned.m8n8.x4.shared.b16 {%0,%1,%2,%3}, [%4];"
                 : "=r"(r[0]), "=r"(r[1]), "=r"(r[2]), "=r"(r[3]) : "r"(addr));
}
__device__ __forceinline__ void ldm_bt(uint32_t* r, uint32_t addr) {
    asm volatile("ldmatrix.sync.aligned.m8n8.x2.trans.shared.b16 {%0,%1}, [%2];"
                 : "=r"(r[0]), "=r"(r[1]) : "r"(addr));
}
__device__ __forceinline__ void cp16(uint32_t s, const void* g) {
    asm volatile("cp.async.cg.shared.global [%0], [%1], 16;" :: "r"(s), "l"(g));
}
#define CP_COMMIT() asm volatile("cp.async.commit_group;")
template <int N>
__device__ __forceinline__ void cp_wait() { asm volatile("cp.async.wait_group %0;" :: "n"(N)); }

__device__ __forceinline__ uint32_t bpack(__nv_bfloat16 a, __nv_bfloat16 b) {
    __nv_bfloat162 t = __halves2bfloat162(a, b);
    return *reinterpret_cast<uint32_t*>(&t);
}
__device__ __forceinline__ void split_pack4(float4 v, uint2& hi, uint2& lo) {
    __nv_bfloat16 h0 = __float2bfloat16(v.x), h1 = __float2bfloat16(v.y);
    __nv_bfloat16 h2 = __float2bfloat16(v.z), h3 = __float2bfloat16(v.w);
    hi.x = bpack(h0, h1); hi.y = bpack(h2, h3);
    lo.x = bpack(__float2bfloat16(v.x - __bfloat162float(h0)),
                 __float2bfloat16(v.y - __bfloat162float(h1)));
    lo.y = bpack(__float2bfloat16(v.z - __bfloat162float(h2)),
                 __float2bfloat16(v.w - __bfloat162float(h3)));
}

// stage one 32-row weight chunk (hi 8704B + lo 8704B) via cp.async
__device__ __forceinline__ void stage_w(uint32_t sb, uint32_t woff, int wrow, int tid) {
    const char* sh = (const char*)(g_w_hi + (size_t)wrow * WPAD);
    const char* sl = (const char*)(g_w_lo + (size_t)wrow * WPAD);
#pragma unroll
    for (int i = 0; i < 3; i++) {
        int j = tid + i * 256;
        if (j < 544) {
            cp16(sb + woff + (uint32_t)j * 16, sh + j * 16);
            cp16(sb + woff + 8704u + (uint32_t)j * 16, sl + j * 16);
        }
    }
    CP_COMMIT();
}

// compute one 32-k chunk: acc[2][4][4] += A[64 x 32] * W[32 x 128]
__device__ __forceinline__ void gemm_chunk(uint32_t sb, uint32_t a_off, uint32_t alo_rel,
                                           uint32_t astr, uint32_t kbase, uint32_t w_off,
                                           int lane, int wm, int wn, float acc[2][4][4]) {
#pragma unroll
    for (int ks = 0; ks < 2; ks++) {
        uint32_t ah[2][4], al[2][4];
        uint32_t colb = (kbase + (uint32_t)ks * 16 + (uint32_t)((lane >> 4) << 3)) * 2;
#pragma unroll
        for (int mt = 0; mt < 2; mt++) {
            uint32_t row = (uint32_t)(wm * 32 + mt * 16 + (lane & 15));
            ldm_a(ah[mt], sb + a_off + row * astr + colb);
            ldm_a(al[mt], sb + a_off + alo_rel + row * astr + colb);
        }
        uint32_t bh[4][2], bl[4][2];
        uint32_t brow = (uint32_t)(ks * 16 + (lane & 15)) * 272u;
#pragma unroll
        for (int nt = 0; nt < 4; nt++) {
            uint32_t nb = (uint32_t)(wn * 32 + nt * 8) * 2;
            ldm_bt(bh[nt], sb + w_off + brow + nb);
            ldm_bt(bl[nt], sb + w_off + 8704u + brow + nb);
        }
#pragma unroll
        for (int mt = 0; mt < 2; mt++)
#pragma unroll
            for (int nt = 0; nt < 4; nt++) {
                mma16816(acc[mt][nt], ah[mt], bh[nt]);
                mma16816(acc[mt][nt], ah[mt], bl[nt]);
                mma16816(acc[mt][nt], al[mt], bh[nt]);
            }
    }
}

// bias + relu -> hi/lo bf16 h image (stride 272B)
__device__ __forceinline__ void epi_relu_split(float acc[2][4][4], const float* __restrict__ bias,
                                               char* smem, int lane, int wm, int wn) {
#pragma unroll
    for (int mt = 0; mt < 2; mt++)
#pragma unroll
        for (int nt = 0; nt < 4; nt++) {
            int n0 = wn * 32 + nt * 8 + (lane & 3) * 2;
            float2 bv = *(const float2*)(bias + n0);
            int r0 = wm * 32 + mt * 16 + (lane >> 2);
            float v0 = fmaxf(acc[mt][nt][0] + bv.x, 0.f);
            float v1 = fmaxf(acc[mt][nt][1] + bv.y, 0.f);
            float v2 = fmaxf(acc[mt][nt][2] + bv.x, 0.f);
            float v3 = fmaxf(acc[mt][nt][3] + bv.y, 0.f);
            __nv_bfloat16 h0 = __float2bfloat16(v0), h1 = __float2bfloat16(v1);
            __nv_bfloat16 h2 = __float2bfloat16(v2), h3 = __float2bfloat16(v3);
            *(uint32_t*)(smem + SM_H + r0 * 272 + n0 * 2) = bpack(h0, h1);
            *(uint32_t*)(smem + SM_H + 17408u + r0 * 272 + n0 * 2) =
                bpack(__float2bfloat16(v0 - __bfloat162float(h0)),
                      __float2bfloat16(v1 - __bfloat162float(h1)));
            *(uint32_t*)(smem + SM_H + (r0 + 8) * 272 + n0 * 2) = bpack(h2, h3);
            *(uint32_t*)(smem + SM_H + 17408u + (r0 + 8) * 272 + n0 * 2) =
                bpack(__float2bfloat16(v2 - __bfloat162float(h2)),
                      __float2bfloat16(v3 - __bfloat162float(h3)));
        }
}

// layer3: bias only -> fp32 staging (stride 528B)
__device__ __forceinline__ void epi_f32(float acc[2][4][4], const float* __restrict__ bias,
                                        char* smem, int lane, int wm, int wn) {
#pragma unroll
    for (int mt = 0; mt < 2; mt++)
#pragma unroll
        for (int nt = 0; nt < 4; nt++) {
            int n0 = wn * 32 + nt * 8 + (lane & 3) * 2;
            float2 bv = *(const float2*)(bias + n0);
            int r0 = wm * 32 + mt * 16 + (lane >> 2);
            *(float2*)(smem + SM_STG + r0 * 528 + n0 * 4) =
                make_float2(acc[mt][nt][0] + bv.x, acc[mt][nt][1] + bv.y);
            *(float2*)(smem + SM_STG + (r0 + 8) * 528 + n0 * 4) =
                make_float2(acc[mt][nt][2] + bv.x, acc[mt][nt][3] + bv.y);
        }
}

template <bool EDGE>
__global__ void __launch_bounds__(256, 2) mlp_kernel(
    const float* __restrict__ nf, const float* __restrict__ ef,
    const int* __restrict__ snd, const int* __restrict__ rcv,
    const float* __restrict__ b1, const float* __restrict__ b2, const float* __restrict__ b3,
    const float* __restrict__ gamma, const float* __restrict__ beta,
    float* __restrict__ out) {
    extern __shared__ char smem[];
    const uint32_t sb = (uint32_t)__cvta_generic_to_shared(smem);
    const int tid = threadIdx.x, lane = tid & 31, wid = tid >> 5;
    const int wm = wid >> 2, wn = wid & 3;
    const size_t base = (size_t)blockIdx.x * 64;
    const size_t LIM = EDGE ? NE : NN;

    int* sidx = (int*)(smem + SM_IDXS);
    int* ridx = (int*)(smem + SM_IDXR);
    if (EDGE && tid < 128) {
        size_t ge = base + (tid & 63);
        int v = (ge < NE) ? ((tid < 64) ? snd[ge] : rcv[ge]) : 0;
        if (tid < 64) sidx[tid] = v; else ridx[tid - 64] = v;
    }
    __syncthreads();

    const int grow = tid >> 2, q = tid & 3;   // gather mapping: 4 threads/row, 8 floats each

    auto do_gather = [&](int g, int buf) {
        const float* src = nf;
        bool zero = false;
        size_t ge = base + grow;
        int seg = g >> 2, col0 = (g & 3) * 32;
        if (EDGE) {
            if (seg == 0)      src = nf + (size_t)sidx[grow] * D + col0;
            else if (seg == 1) src = nf + (size_t)ridx[grow] * D + col0;
            else               src = ef + ge * D + col0;
        } else {
            zero = (ge >= NN);
            src = (seg == 0 ? nf : g_agg) + (zero ? 0 : ge * D) + col0;
        }
        float4 va = zero ? make_float4(0.f, 0.f, 0.f, 0.f) : *(const float4*)(src + q * 8);
        float4 vb = zero ? make_float4(0.f, 0.f, 0.f, 0.f) : *(const float4*)(src + q * 8 + 4);
        uint2 hi, lo;
        uint32_t off = XOFF(buf) + (uint32_t)grow * XSTR + (uint32_t)q * 16;
        split_pack4(va, hi, lo);
        *(uint2*)(smem + off) = hi;
        *(uint2*)(smem + off + 5120u) = lo;
        split_pack4(vb, hi, lo);
        *(uint2*)(smem + off + 8u) = hi;
        *(uint2*)(smem + off + 5120u + 8u) = lo;
    };

    const int L1 = EDGE ? 12 : 8;       // 32-k chunks in layer 1
    const int NCH = L1 + 8;             // + 4 (L2) + 4 (L3)
    const int WR0 = EDGE ? 0 : 640;

    float acc[2][4][4];
#pragma unroll
    for (int mt = 0; mt < 2; mt++)
#pragma unroll
        for (int nt = 0; nt < 4; nt++)
#pragma unroll
            for (int i = 0; i < 4; i++) acc[mt][nt][i] = 0.f;

    for (int g = 0; g < NCH; g++) {
        const int buf = g & 1;
        __syncthreads();   // readers of buf^1 (chunk g-1) done before refill below
        if (g == 0) { do_gather(0, 0); stage_w(sb, WOFF(0), WR0, tid); }
        if (g + 1 < NCH) {
            if (g + 1 < L1) do_gather(g + 1, buf ^ 1);
            stage_w(sb, WOFF(buf ^ 1), WR0 + (g + 1) * 32, tid);
            cp_wait<1>();
        } else {
            cp_wait<0>();
        }
        __syncthreads();

        uint32_t a_off, alo_rel, astr, kbase;
        if (g < L1) { a_off = XOFF(buf); alo_rel = 5120u; astr = XSTR; kbase = 0; }
        else { a_off = SM_H; alo_rel = 17408u; astr = 272u; kbase = (uint32_t)((g - L1) & 3) * 32u; }
        gemm_chunk(sb, a_off, alo_rel, astr, kbase, WOFF(buf), lane, wm, wn, acc);

        if (g == L1 - 1 || g == L1 + 3) {
            __syncthreads();   // all reads of h complete before it is overwritten
            epi_relu_split(acc, (g == L1 - 1) ? b1 : b2, smem, lane, wm, wn);
#pragma unroll
            for (int mt = 0; mt < 2; mt++)
#pragma unroll
                for (int nt = 0; nt < 4; nt++)
#pragma unroll
                    for (int i = 0; i < 4; i++) acc[mt][nt][i] = 0.f;
        }
    }
    __syncthreads();
    epi_f32(acc, b3, smem, lane, wm, wn);   // staging aliases dead stream buffers
    __syncthreads();

    // LN + residual (+ scatter for edges)
    const int ccg = tid & 15, ecg = tid >> 4;
    float4 g0 = *(const float4*)(gamma + ccg * 8), g1 = *(const float4*)(gamma + ccg * 8 + 4);
    float4 t0 = *(const float4*)(beta + ccg * 8),  t1 = *(const float4*)(beta + ccg * 8 + 4);
    float gv[8] = {g0.x, g0.y, g0.z, g0.w, g1.x, g1.y, g1.z, g1.w};
    float bv[8] = {t0.x, t0.y, t0.z, t0.w, t1.x, t1.y, t1.z, t1.w};
#pragma unroll
    for (int ei = 0; ei < 4; ei++) {
        int el = ecg * 4 + ei;
        size_t ge = base + el;
        float4 p0 = *(float4*)(smem + SM_STG + (uint32_t)el * 528 + ccg * 32);
        float4 p1 = *(float4*)(smem + SM_STG + (uint32_t)el * 528 + ccg * 32 + 16);
        float v[8] = {p0.x, p0.y, p0.z, p0.w, p1.x, p1.y, p1.z, p1.w};
        float s = 0.f, s2 = 0.f;
#pragma unroll
        for (int c = 0; c < 8; c++) { s += v[c]; s2 += v[c] * v[c]; }
#pragma unroll
        for (int m = 8; m >= 1; m >>= 1) {
            s  += __shfl_xor_sync(0xffffffffu, s, m);
            s2 += __shfl_xor_sync(0xffffffffu, s2, m);
        }
        if (ge >= LIM) continue;
        float mu = s * (1.f / D), var = s2 * (1.f / D) - mu * mu;
        float rstd = rsqrtf(fmaxf(var, 0.f) + 1e-5f);
        float nrm[8];
#pragma unroll
        for (int c = 0; c < 8; c++) nrm[c] = (v[c] - mu) * rstd * gv[c] + bv[c];
        if (EDGE) {
            float* ap = g_agg + (size_t)ridx[el] * D + ccg * 8;
            asm volatile("red.global.add.v4.f32 [%0], {%1,%2,%3,%4};" ::
                         "l"(ap), "f"(nrm[0]), "f"(nrm[1]), "f"(nrm[2]), "f"(nrm[3]) : "memory");
            asm volatile("red.global.add.v4.f32 [%0], {%1,%2,%3,%4};" ::
                         "l"(ap + 4), "f"(nrm[4]), "f"(nrm[5]), "f"(nrm[6]), "f"(nrm[7]) : "memory");
        }
        const float* res = (EDGE ? ef : nf) + ge * D + ccg * 8;
        float4 e0 = *(const float4*)res, e1 = *(const float4*)(res + 4);
        float* op = out + ge * D + ccg * 8;
        *(float4*)op       = make_float4(nrm[0] + e0.x, nrm[1] + e0.y, nrm[2] + e0.z, nrm[3] + e0.w);
        *(float4*)(op + 4) = make_float4(nrm[4] + e1.x, nrm[5] + e1.y, nrm[6] + e1.z, nrm[7] + e1.w);
    }
}

extern "C" void kernel_launch(void* const* d_in, const int* in_sizes, int n_in,
                              void* d_out, int out_size) {
    const float* nf  = (const float*)d_in[0];
    const float* ef  = (const float*)d_in[1];
    const int*   snd = (const int*)d_in[2];
    const int*   rcv = (const int*)d_in[3];
    const float* ew1 = (const float*)d_in[4];
    const float* eb1 = (const float*)d_in[5];
    const float* ew2 = (const float*)d_in[6];
    const float* eb2 = (const float*)d_in[7];
    const float* ew3 = (const float*)d_in[8];
    const float* eb3 = (const float*)d_in[9];
    const float* eg  = (const float*)d_in[10];
    const float* ebt = (const float*)d_in[11];
    const float* nw1 = (const float*)d_in[12];
    const float* nb1 = (const float*)d_in[13];
    const float* nw2 = (const float*)d_in[14];
    const float* nb2 = (const float*)d_in[15];
    const float* nw3 = (const float*)d_in[16];
    const float* nb3 = (const float*)d_in[17];
    const float* ng  = (const float*)d_in[18];
    const float* nbt = (const float*)d_in[19];

    float* out_n = (float*)d_out;
    float* out_e = out_n + (size_t)NN * D;

    cudaFuncSetAttribute(mlp_kernel<true>,  cudaFuncAttributeMaxDynamicSharedMemorySize, SMEM_TOTAL);
    cudaFuncSetAttribute(mlp_kernel<false>, cudaFuncAttributeMaxDynamicSharedMemorySize, SMEM_TOTAL);

    prep_weights<<<612, 256>>>(ew1, ew2, ew3, nw1, nw2, nw3);
    zero_agg_kernel<<<NN * D / 4 / 256, 256>>>();
    mlp_kernel<true><<<NE / 64, 256, SMEM_TOTAL>>>(nf, ef, snd, rcv,
                                                   eb1, eb2, eb3, eg, ebt, out_e);
    mlp_kernel<false><<<(NN + 63) / 64, 256, SMEM_TOTAL>>>(nf, ef, snd, rcv,
                                                           nb1, nb2, nb3, ng, nbt, out_n);
}

// round 7
// speedup vs baseline: 5.1033x; 1.0809x over previous
#include <cuda_runtime.h>
#include <cuda_bf16.h>
#include <cstdint>

#define NN 100000
#define NE 600000
#define D  128
#define WPAD 136            // weight row width (272B rows)

// smem layout (bytes): two stream buffers [X(10240: hi 5120|lo 5120) + W(17408: hi 8704|lo 8704)]
// then h (hi 17408 | lo 17408). LN staging (64*528=33792) aliases stream buffers.
#define XSTR   80u
#define BUFSZ  27648u
#define XOFF(b) ((uint32_t)(b) * BUFSZ)
#define WOFF(b) ((uint32_t)(b) * BUFSZ + 10240u)
#define SM_H    55296u
#define SM_STG  0u
#define SM_IDXS 90112u
#define SM_IDXR 90368u
#define SMEM_TOTAL 90624

__device__ float g_agg[(size_t)NN * D];
// stacked pre-split weights (rows x 272B): [0,384) ew1 | [384,512) ew2 | [512,640) ew3 |
// [640,896) nw1[0:256] | [896,1024) nw2 | [1024,1152) nw3
__device__ __nv_bfloat16 g_w_hi[1152 * WPAD];
__device__ __nv_bfloat16 g_w_lo[1152 * WPAD];

__global__ void zero_agg_kernel() {
    size_t i = (size_t)blockIdx.x * blockDim.x + threadIdx.x;
    ((float4*)g_agg)[i] = make_float4(0.f, 0.f, 0.f, 0.f);
}

__global__ void prep_weights(const float* __restrict__ ew1, const float* __restrict__ ew2,
                             const float* __restrict__ ew3, const float* __restrict__ nw1,
                             const float* __restrict__ nw2, const float* __restrict__ nw3) {
    int idx = blockIdx.x * 256 + threadIdx.x;
    if (idx >= 1152 * WPAD) return;
    int r = idx / WPAD, c = idx % WPAD;
    float v = 0.f;
    if (c < 128) {
        if (r < 384)       v = ew1[r * 128 + c];
        else if (r < 512)  v = ew2[(r - 384) * 128 + c];
        else if (r < 640)  v = ew3[(r - 512) * 128 + c];
        else if (r < 896)  v = nw1[(r - 640) * 128 + c];
        else if (r < 1024) v = nw2[(r - 896) * 128 + c];
        else               v = nw3[(r - 1024) * 128 + c];
    }
    __nv_bfloat16 h = __float2bfloat16(v);
    g_w_hi[idx] = h;
    g_w_lo[idx] = __float2bfloat16(v - __bfloat162float(h));
}

// ---------------- helpers ----------------
__device__ __forceinline__ void mma16816(float* c, const uint32_t* a, const uint32_t* b) {
    asm volatile(
        "mma.sync.aligned.m16n8k16.row.col.f32.bf16.bf16.f32 "
        "{%0,%1,%2,%3}, {%4,%5,%6,%7}, {%8,%9}, {%0,%1,%2,%3};"
        : "+f"(c[0]), "+f"(c[1]), "+f"(c[2]), "+f"(c[3])
        : "r"(a[0]), "r"(a[1]), "r"(a[2]), "r"(a[3]), "r"(b[0]), "r"(b[1]));
}
__device__ __forceinline__ void ldm_a(uint32_t* r, uint32_t addr) {
    asm volatile("ldmatrix.sync.aligned.m8n8.x4.shared.b16 {%0,%1,%2,%3}, [%4];"
                 : "=r"(r[0]), "=r"(r[1]), "=r"(r[2]), "=r"(r[3]) : "r"(addr));
}
__device__ __forceinline__ void ldm_bt4(uint32_t* r, uint32_t addr) {
    asm volatile("ldmatrix.sync.aligned.m8n8.x4.trans.shared.b16 {%0,%1,%2,%3}, [%4];"
                 : "=r"(r[0]), "=r"(r[1]), "=r"(r[2]), "=r"(r[3]) : "r"(addr));
}
__device__ __forceinline__ void cp16(uint32_t s, const void* g) {
    asm volatile("cp.async.cg.shared.global [%0], [%1], 16;" :: "r"(s), "l"(g));
}
#define CP_COMMIT() asm volatile("cp.async.commit_group;")
template <int N>
__device__ __forceinline__ void cp_wait() { asm volatile("cp.async.wait_group %0;" :: "n"(N)); }

__device__ __forceinline__ uint32_t bpack(__nv_bfloat16 a, __nv_bfloat16 b) {
    __nv_bfloat162 t = __halves2bfloat162(a, b);
    return *reinterpret_cast<uint32_t*>(&t);
}
__device__ __forceinline__ void split_pack4(float4 v, uint2& hi, uint2& lo) {
    __nv_bfloat16 h0 = __float2bfloat16(v.x), h1 = __float2bfloat16(v.y);
    __nv_bfloat16 h2 = __float2bfloat16(v.z), h3 = __float2bfloat16(v.w);
    hi.x = bpack(h0, h1); hi.y = bpack(h2, h3);
    lo.x = bpack(__float2bfloat16(v.x - __bfloat162float(h0)),
                 __float2bfloat16(v.y - __bfloat162float(h1)));
    lo.y = bpack(__float2bfloat16(v.z - __bfloat162float(h2)),
                 __float2bfloat16(v.w - __bfloat162float(h3)));
}

// stage one 32-row weight chunk (hi 8704B + lo 8704B) via cp.async
__device__ __forceinline__ void stage_w(uint32_t sb, uint32_t woff, int wrow, int tid) {
    const char* sh = (const char*)(g_w_hi + (size_t)wrow * WPAD);
    const char* sl = (const char*)(g_w_lo + (size_t)wrow * WPAD);
#pragma unroll
    for (int i = 0; i < 3; i++) {
        int j = tid + i * 256;
        if (j < 544) {
            cp16(sb + woff + (uint32_t)j * 16, sh + j * 16);
            cp16(sb + woff + 8704u + (uint32_t)j * 16, sl + j * 16);
        }
    }
    CP_COMMIT();
}

// compute one 32-k chunk: acc[2][4][4] += A[64 x 32] * W[32 x 128]
// B loaded once per chunk via x4.trans (k=32 per nt/plane).
__device__ __forceinline__ void gemm_chunk(uint32_t sb, uint32_t a_off, uint32_t alo_rel,
                                           uint32_t astr, uint32_t kbase, uint32_t w_off,
                                           int lane, int wm, int wn, float acc[2][4][4]) {
    uint32_t bh[4][4], bl[4][4];
    uint32_t brow = (uint32_t)lane * 272u;
#pragma unroll
    for (int nt = 0; nt < 4; nt++) {
        uint32_t nb = (uint32_t)(wn * 32 + nt * 8) * 2;
        ldm_bt4(bh[nt], sb + w_off + brow + nb);
        ldm_bt4(bl[nt], sb + w_off + 8704u + brow + nb);
    }
#pragma unroll
    for (int ks = 0; ks < 2; ks++) {
        uint32_t ah[2][4], al[2][4];
        uint32_t colb = (kbase + (uint32_t)ks * 16 + (uint32_t)((lane >> 4) << 3)) * 2;
#pragma unroll
        for (int mt = 0; mt < 2; mt++) {
            uint32_t row = (uint32_t)(wm * 32 + mt * 16 + (lane & 15));
            ldm_a(ah[mt], sb + a_off + row * astr + colb);
            ldm_a(al[mt], sb + a_off + alo_rel + row * astr + colb);
        }
#pragma unroll
        for (int mt = 0; mt < 2; mt++)
#pragma unroll
            for (int nt = 0; nt < 4; nt++) {
                mma16816(acc[mt][nt], ah[mt], &bh[nt][ks * 2]);
                mma16816(acc[mt][nt], ah[mt], &bl[nt][ks * 2]);
                mma16816(acc[mt][nt], al[mt], &bh[nt][ks * 2]);
            }
    }
}

// bias + relu -> hi/lo bf16 h image (stride 272B)
__device__ __forceinline__ void epi_relu_split(float acc[2][4][4], const float* __restrict__ bias,
                                               char* smem, int lane, int wm, int wn) {
#pragma unroll
    for (int mt = 0; mt < 2; mt++)
#pragma unroll
        for (int nt = 0; nt < 4; nt++) {
            int n0 = wn * 32 + nt * 8 + (lane & 3) * 2;
            float2 bv = *(const float2*)(bias + n0);
            int r0 = wm * 32 + mt * 16 + (lane >> 2);
            float v0 = fmaxf(acc[mt][nt][0] + bv.x, 0.f);
            float v1 = fmaxf(acc[mt][nt][1] + bv.y, 0.f);
            float v2 = fmaxf(acc[mt][nt][2] + bv.x, 0.f);
            float v3 = fmaxf(acc[mt][nt][3] + bv.y, 0.f);
            __nv_bfloat16 h0 = __float2bfloat16(v0), h1 = __float2bfloat16(v1);
            __nv_bfloat16 h2 = __float2bfloat16(v2), h3 = __float2bfloat16(v3);
            *(uint32_t*)(smem + SM_H + r0 * 272 + n0 * 2) = bpack(h0, h1);
            *(uint32_t*)(smem + SM_H + 17408u + r0 * 272 + n0 * 2) =
                bpack(__float2bfloat16(v0 - __bfloat162float(h0)),
                      __float2bfloat16(v1 - __bfloat162float(h1)));
            *(uint32_t*)(smem + SM_H + (r0 + 8) * 272 + n0 * 2) = bpack(h2, h3);
            *(uint32_t*)(smem + SM_H + 17408u + (r0 + 8) * 272 + n0 * 2) =
                bpack(__float2bfloat16(v2 - __bfloat162float(h2)),
                      __float2bfloat16(v3 - __bfloat162float(h3)));
        }
}

// layer3: bias only -> fp32 staging (stride 528B)
__device__ __forceinline__ void epi_f32(float acc[2][4][4], const float* __restrict__ bias,
                                        char* smem, int lane, int wm, int wn) {
#pragma unroll
    for (int mt = 0; mt < 2; mt++)
#pragma unroll
        for (int nt = 0; nt < 4; nt++) {
            int n0 = wn * 32 + nt * 8 + (lane & 3) * 2;
            float2 bv = *(const float2*)(bias + n0);
            int r0 = wm * 32 + mt * 16 + (lane >> 2);
            *(float2*)(smem + SM_STG + r0 * 528 + n0 * 4) =
                make_float2(acc[mt][nt][0] + bv.x, acc[mt][nt][1] + bv.y);
            *(float2*)(smem + SM_STG + (r0 + 8) * 528 + n0 * 4) =
                make_float2(acc[mt][nt][2] + bv.x, acc[mt][nt][3] + bv.y);
        }
}

template <bool EDGE>
__global__ void __launch_bounds__(256, 2) mlp_kernel(
    const float* __restrict__ nf, const float* __restrict__ ef,
    const int* __restrict__ snd, const int* __restrict__ rcv,
    const float* __restrict__ b1, const float* __restrict__ b2, const float* __restrict__ b3,
    const float* __restrict__ gamma, const float* __restrict__ beta,
    float* __restrict__ out) {
    extern __shared__ char smem[];
    const uint32_t sb = (uint32_t)__cvta_generic_to_shared(smem);
    const int tid = threadIdx.x, lane = tid & 31, wid = tid >> 5;
    const int wm = wid >> 2, wn = wid & 3;
    const size_t base = (size_t)blockIdx.x * 64;
    const size_t LIM = EDGE ? NE : NN;

    int* sidx = (int*)(smem + SM_IDXS);
    int* ridx = (int*)(smem + SM_IDXR);
    if (EDGE && tid < 128) {
        size_t ge = base + (tid & 63);
        int v = (ge < NE) ? ((tid < 64) ? snd[ge] : rcv[ge]) : 0;
        if (tid < 64) sidx[tid] = v; else ridx[tid - 64] = v;
    }
    __syncthreads();

    const int grow = tid >> 2, q = tid & 3;   // gather mapping: 4 threads/row, 8 floats each

    float4 pre0, pre1;                        // prefetched gather regs (chunk g+1)
    auto ldg_chunk = [&](int g) {
        const float* src = nf;
        bool zero = false;
        size_t ge = base + grow;
        int seg = g >> 2, col0 = (g & 3) * 32;
        if (EDGE) {
            if (seg == 0)      src = nf + (size_t)sidx[grow] * D + col0;
            else if (seg == 1) src = nf + (size_t)ridx[grow] * D + col0;
            else               src = ef + ge * D + col0;
        } else {
            zero = (ge >= NN);
            src = (seg == 0 ? nf : g_agg) + (zero ? 0 : ge * D) + col0;
        }
        pre0 = zero ? make_float4(0.f, 0.f, 0.f, 0.f) : *(const float4*)(src + q * 8);
        pre1 = zero ? make_float4(0.f, 0.f, 0.f, 0.f) : *(const float4*)(src + q * 8 + 4);
    };
    auto sts_chunk = [&](int buf) {
        uint2 hi, lo;
        uint32_t off = XOFF(buf) + (uint32_t)grow * XSTR + (uint32_t)q * 16;
        split_pack4(pre0, hi, lo);
        *(uint2*)(smem + off) = hi;
        *(uint2*)(smem + off + 5120u) = lo;
        split_pack4(pre1, hi, lo);
        *(uint2*)(smem + off + 8u) = hi;
        *(uint2*)(smem + off + 5120u + 8u) = lo;
    };

    const int L1 = EDGE ? 12 : 8;       // 32-k chunks in layer 1
    const int NCH = L1 + 8;             // + 4 (L2) + 4 (L3)
    const int WR0 = EDGE ? 0 : 640;

    float acc[2][4][4];
#pragma unroll
    for (int mt = 0; mt < 2; mt++)
#pragma unroll
        for (int nt = 0; nt < 4; nt++)
#pragma unroll
            for (int i = 0; i < 4; i++) acc[mt][nt][i] = 0.f;

    ldg_chunk(0);                       // prefetch chunk 0

    for (int g = 0; g < NCH; g++) {
        const int buf = g & 1;
        __syncthreads();   // buffer buf free (gemm g-2 done); h/epi writes ordered
        if (g < L1) sts_chunk(buf);            // convert + STS chunk g (from prefetch regs)
        if (g + 1 < L1) ldg_chunk(g + 1);      // issue next gather; hidden behind gemm(g)
        if (g == 0) stage_w(sb, WOFF(0), WR0, tid);
        if (g + 1 < NCH) {
            stage_w(sb, WOFF(buf ^ 1), WR0 + (g + 1) * 32, tid);
            cp_wait<1>();
        } else {
            cp_wait<0>();
        }
        __syncthreads();

        uint32_t a_off, alo_rel, astr, kbase;
        if (g < L1) { a_off = XOFF(buf); alo_rel = 5120u; astr = XSTR; kbase = 0; }
        else { a_off = SM_H; alo_rel = 17408u; astr = 272u; kbase = (uint32_t)((g - L1) & 3) * 32u; }
        gemm_chunk(sb, a_off, alo_rel, astr, kbase, WOFF(buf), lane, wm, wn, acc);

        if (g == L1 - 1 || g == L1 + 3) {
            __syncthreads();   // all reads of h complete before it is overwritten
            epi_relu_split(acc, (g == L1 - 1) ? b1 : b2, smem, lane, wm, wn);
#pragma unroll
            for (int mt = 0; mt < 2; mt++)
#pragma unroll
                for (int nt = 0; nt < 4; nt++)
#pragma unroll
                    for (int i = 0; i < 4; i++) acc[mt][nt][i] = 0.f;
        }
    }
    __syncthreads();
    epi_f32(acc, b3, smem, lane, wm, wn);   // staging aliases dead stream buffers
    __syncthreads();

    // LN + residual (+ scatter for edges)
    const int ccg = tid & 15, ecg = tid >> 4;
    float4 g0 = *(const float4*)(gamma + ccg * 8), g1 = *(const float4*)(gamma + ccg * 8 + 4);
    float4 t0 = *(const float4*)(beta + ccg * 8),  t1 = *(const float4*)(beta + ccg * 8 + 4);
    float gv[8] = {g0.x, g0.y, g0.z, g0.w, g1.x, g1.y, g1.z, g1.w};
    float bv[8] = {t0.x, t0.y, t0.z, t0.w, t1.x, t1.y, t1.z, t1.w};
#pragma unroll
    for (int ei = 0; ei < 4; ei++) {
        int el = ecg * 4 + ei;
        size_t ge = base + el;
        float4 p0 = *(float4*)(smem + SM_STG + (uint32_t)el * 528 + ccg * 32);
        float4 p1 = *(float4*)(smem + SM_STG + (uint32_t)el * 528 + ccg * 32 + 16);
        float v[8] = {p0.x, p0.y, p0.z, p0.w, p1.x, p1.y, p1.z, p1.w};
        float s = 0.f, s2 = 0.f;
#pragma unroll
        for (int c = 0; c < 8; c++) { s += v[c]; s2 += v[c] * v[c]; }
#pragma unroll
        for (int m = 8; m >= 1; m >>= 1) {
            s  += __shfl_xor_sync(0xffffffffu, s, m);
            s2 += __shfl_xor_sync(0xffffffffu, s2, m);
        }
        if (ge >= LIM) continue;
        float mu = s * (1.f / D), var = s2 * (1.f / D) - mu * mu;
        float rstd = rsqrtf(fmaxf(var, 0.f) + 1e-5f);
        float nrm[8];
#pragma unroll
        for (int c = 0; c < 8; c++) nrm[c] = (v[c] - mu) * rstd * gv[c] + bv[c];
        if (EDGE) {
            float* ap = g_agg + (size_t)ridx[el] * D + ccg * 8;
            asm volatile("red.global.add.v4.f32 [%0], {%1,%2,%3,%4};" ::
                         "l"(ap), "f"(nrm[0]), "f"(nrm[1]), "f"(nrm[2]), "f"(nrm[3]) : "memory");
            asm volatile("red.global.add.v4.f32 [%0], {%1,%2,%3,%4};" ::
                         "l"(ap + 4), "f"(nrm[4]), "f"(nrm[5]), "f"(nrm[6]), "f"(nrm[7]) : "memory");
        }
        const float* res = (EDGE ? ef : nf) + ge * D + ccg * 8;
        float4 e0 = *(const float4*)res, e1 = *(const float4*)(res + 4);
        float* op = out + ge * D + ccg * 8;
        *(float4*)op       = make_float4(nrm[0] + e0.x, nrm[1] + e0.y, nrm[2] + e0.z, nrm[3] + e0.w);
        *(float4*)(op + 4) = make_float4(nrm[4] + e1.x, nrm[5] + e1.y, nrm[6] + e1.z, nrm[7] + e1.w);
    }
}

extern "C" void kernel_launch(void* const* d_in, const int* in_sizes, int n_in,
                              void* d_out, int out_size) {
    const float* nf  = (const float*)d_in[0];
    const float* ef  = (const float*)d_in[1];
    const int*   snd = (const int*)d_in[2];
    const int*   rcv = (const int*)d_in[3];
    const float* ew1 = (const float*)d_in[4];
    const float* eb1 = (const float*)d_in[5];
    const float* ew2 = (const float*)d_in[6];
    const float* eb2 = (const float*)d_in[7];
    const float* ew3 = (const float*)d_in[8];
    const float* eb3 = (const float*)d_in[9];
    const float* eg  = (const float*)d_in[10];
    const float* ebt = (const float*)d_in[11];
    const float* nw1 = (const float*)d_in[12];
    const float* nb1 = (const float*)d_in[13];
    const float* nw2 = (const float*)d_in[14];
    const float* nb2 = (const float*)d_in[15];
    const float* nw3 = (const float*)d_in[16];
    const float* nb3 = (const float*)d_in[17];
    const float* ng  = (const float*)d_in[18];
    const float* nbt = (const float*)d_in[19];

    float* out_n = (float*)d_out;
    float* out_e = out_n + (size_t)NN * D;

    cudaFuncSetAttribute(mlp_kernel<true>,  cudaFuncAttributeMaxDynamicSharedMemorySize, SMEM_TOTAL);
    cudaFuncSetAttribute(mlp_kernel<false>, cudaFuncAttributeMaxDynamicSharedMemorySize, SMEM_TOTAL);

    prep_weights<<<612, 256>>>(ew1, ew2, ew3, nw1, nw2, nw3);
    zero_agg_kernel<<<NN * D / 4 / 256, 256>>>();
    mlp_kernel<true><<<NE / 64, 256, SMEM_TOTAL>>>(nf, ef, snd, rcv,
                                                   eb1, eb2, eb3, eg, ebt, out_e);
    mlp_kernel<false><<<(NN + 63) / 64, 256, SMEM_TOTAL>>>(nf, ef, snd, rcv,
                                                           nb1, nb2, nb3, ng, nbt, out_n);
}

// round 8
// speedup vs baseline: 6.5403x; 1.2816x over previous
#include <cuda_runtime.h>
#include <cuda_fp16.h>
#include <cstdint>

#define NN 100000
#define NE 600000
#define D  128
#define WPAD 136            // weight row width (272B rows)

// smem layout (bytes): two stream buffers [X(10240: hi 5120|lo 5120) + W(8704)]
// then h (hi 17408 | lo 17408). LN staging (64*528=33792) aliases stream buffers.
#define XSTR   80u
#define BUFSZ  18944u
#define XOFF(b) ((uint32_t)(b) * BUFSZ)
#define WOFF(b) ((uint32_t)(b) * BUFSZ + 10240u)
#define SM_H    37888u
#define SM_STG  0u
#define SM_IDXS 72704u
#define SM_IDXR 72960u
#define SMEM_TOTAL 73216

__device__ float g_agg[(size_t)NN * D];
// stacked fp16 weights (rows x 272B): [0,384) ew1 | [384,512) ew2 | [512,640) ew3 |
// [640,896) nw1[0:256] | [896,1024) nw2 | [1024,1152) nw3
__device__ __half g_w[1152 * WPAD];

__global__ void zero_agg_kernel() {
    size_t i = (size_t)blockIdx.x * blockDim.x + threadIdx.x;
    ((float4*)g_agg)[i] = make_float4(0.f, 0.f, 0.f, 0.f);
}

__global__ void prep_weights(const float* __restrict__ ew1, const float* __restrict__ ew2,
                             const float* __restrict__ ew3, const float* __restrict__ nw1,
                             const float* __restrict__ nw2, const float* __restrict__ nw3) {
    int idx = blockIdx.x * 256 + threadIdx.x;
    if (idx >= 1152 * WPAD) return;
    int r = idx / WPAD, c = idx % WPAD;
    float v = 0.f;
    if (c < 128) {
        if (r < 384)       v = ew1[r * 128 + c];
        else if (r < 512)  v = ew2[(r - 384) * 128 + c];
        else if (r < 640)  v = ew3[(r - 512) * 128 + c];
        else if (r < 896)  v = nw1[(r - 640) * 128 + c];
        else if (r < 1024) v = nw2[(r - 896) * 128 + c];
        else               v = nw3[(r - 1024) * 128 + c];
    }
    g_w[idx] = __float2half_rn(v);
}

// ---------------- helpers ----------------
__device__ __forceinline__ void mma16816(float* c, const uint32_t* a, const uint32_t* b) {
    asm volatile(
        "mma.sync.aligned.m16n8k16.row.col.f32.f16.f16.f32 "
        "{%0,%1,%2,%3}, {%4,%5,%6,%7}, {%8,%9}, {%0,%1,%2,%3};"
        : "+f"(c[0]), "+f"(c[1]), "+f"(c[2]), "+f"(c[3])
        : "r"(a[0]), "r"(a[1]), "r"(a[2]), "r"(a[3]), "r"(b[0]), "r"(b[1]));
}
__device__ __forceinline__ void ldm_a(uint32_t* r, uint32_t addr) {
    asm volatile("ldmatrix.sync.aligned.m8n8.x4.shared.b16 {%0,%1,%2,%3}, [%4];"
                 : "=r"(r[0]), "=r"(r[1]), "=r"(r[2]), "=r"(r[3]) : "r"(addr));
}
__device__ __forceinline__ void ldm_bt4(uint32_t* r, uint32_t addr) {
    asm volatile("ldmatrix.sync.aligned.m8n8.x4.trans.shared.b16 {%0,%1,%2,%3}, [%4];"
                 : "=r"(r[0]), "=r"(r[1]), "=r"(r[2]), "=r"(r[3]) : "r"(addr));
}
__device__ __forceinline__ void cp16(uint32_t s, const void* g) {
    asm volatile("cp.async.cg.shared.global [%0], [%1], 16;" :: "r"(s), "l"(g));
}
#define CP_COMMIT() asm volatile("cp.async.commit_group;")
template <int N>
__device__ __forceinline__ void cp_wait() { asm volatile("cp.async.wait_group %0;" :: "n"(N)); }

__device__ __forceinline__ uint32_t hpack(__half a, __half b) {
    __half2 t = __halves2half2(a, b);
    return *reinterpret_cast<uint32_t*>(&t);
}
__device__ __forceinline__ void split_pack4(float4 v, uint2& hi, uint2& lo) {
    __half h0 = __float2half_rn(v.x), h1 = __float2half_rn(v.y);
    __half h2 = __float2half_rn(v.z), h3 = __float2half_rn(v.w);
    hi.x = hpack(h0, h1); hi.y = hpack(h2, h3);
    lo.x = hpack(__float2half_rn(v.x - __half2float(h0)),
                 __float2half_rn(v.y - __half2float(h1)));
    lo.y = hpack(__float2half_rn(v.z - __half2float(h2)),
                 __float2half_rn(v.w - __half2float(h3)));
}

// stage one 32-row fp16 weight chunk (8704B) via cp.async
__device__ __forceinline__ void stage_w(uint32_t sb, uint32_t woff, int wrow, int tid) {
    const char* sw = (const char*)(g_w + (size_t)wrow * WPAD);
#pragma unroll
    for (int i = 0; i < 3; i++) {
        int j = tid + i * 256;
        if (j < 544) cp16(sb + woff + (uint32_t)j * 16, sw + j * 16);
    }
    CP_COMMIT();
}

// compute one 32-k chunk: acc[2][4][4] += A[64 x 32] * W[32 x 128]
// B loaded once per chunk via x4.trans; 2 mma per (mt,nt,ks): xh*w + xl*w.
__device__ __forceinline__ void gemm_chunk(uint32_t sb, uint32_t a_off, uint32_t alo_rel,
                                           uint32_t astr, uint32_t kbase, uint32_t w_off,
                                           int lane, int wm, int wn, float acc[2][4][4]) {
    uint32_t bw[4][4];
    uint32_t brow = (uint32_t)lane * 272u;
#pragma unroll
    for (int nt = 0; nt < 4; nt++) {
        uint32_t nb = (uint32_t)(wn * 32 + nt * 8) * 2;
        ldm_bt4(bw[nt], sb + w_off + brow + nb);
    }
#pragma unroll
    for (int ks = 0; ks < 2; ks++) {
        uint32_t ah[2][4], al[2][4];
        uint32_t colb = (kbase + (uint32_t)ks * 16 + (uint32_t)((lane >> 4) << 3)) * 2;
#pragma unroll
        for (int mt = 0; mt < 2; mt++) {
            uint32_t row = (uint32_t)(wm * 32 + mt * 16 + (lane & 15));
            ldm_a(ah[mt], sb + a_off + row * astr + colb);
            ldm_a(al[mt], sb + a_off + alo_rel + row * astr + colb);
        }
#pragma unroll
        for (int mt = 0; mt < 2; mt++)
#pragma unroll
            for (int nt = 0; nt < 4; nt++) {
                mma16816(acc[mt][nt], ah[mt], &bw[nt][ks * 2]);
                mma16816(acc[mt][nt], al[mt], &bw[nt][ks * 2]);
            }
    }
}

// bias + relu -> hi/lo fp16 h image (stride 272B)
__device__ __forceinline__ void epi_relu_split(float acc[2][4][4], const float* __restrict__ bias,
                                               char* smem, int lane, int wm, int wn) {
#pragma unroll
    for (int mt = 0; mt < 2; mt++)
#pragma unroll
        for (int nt = 0; nt < 4; nt++) {
            int n0 = wn * 32 + nt * 8 + (lane & 3) * 2;
            float2 bv = *(const float2*)(bias + n0);
            int r0 = wm * 32 + mt * 16 + (lane >> 2);
            float v0 = fmaxf(acc[mt][nt][0] + bv.x, 0.f);
            float v1 = fmaxf(acc[mt][nt][1] + bv.y, 0.f);
            float v2 = fmaxf(acc[mt][nt][2] + bv.x, 0.f);
            float v3 = fmaxf(acc[mt][nt][3] + bv.y, 0.f);
            __half h0 = __float2half_rn(v0), h1 = __float2half_rn(v1);
            __half h2 = __float2half_rn(v2), h3 = __float2half_rn(v3);
            *(uint32_t*)(smem + SM_H + r0 * 272 + n0 * 2) = hpack(h0, h1);
            *(uint32_t*)(smem + SM_H + 17408u + r0 * 272 + n0 * 2) =
                hpack(__float2half_rn(v0 - __half2float(h0)),
                      __float2half_rn(v1 - __half2float(h1)));
            *(uint32_t*)(smem + SM_H + (r0 + 8) * 272 + n0 * 2) = hpack(h2, h3);
            *(uint32_t*)(smem + SM_H + 17408u + (r0 + 8) * 272 + n0 * 2) =
                hpack(__float2half_rn(v2 - __half2float(h2)),
                      __float2half_rn(v3 - __half2float(h3)));
        }
}

// layer3: bias only -> fp32 staging (stride 528B)
__device__ __forceinline__ void epi_f32(float acc[2][4][4], const float* __restrict__ bias,
                                        char* smem, int lane, int wm, int wn) {
#pragma unroll
    for (int mt = 0; mt < 2; mt++)
#pragma unroll
        for (int nt = 0; nt < 4; nt++) {
            int n0 = wn * 32 + nt * 8 + (lane & 3) * 2;
            float2 bv = *(const float2*)(bias + n0);
            int r0 = wm * 32 + mt * 16 + (lane >> 2);
            *(float2*)(smem + SM_STG + r0 * 528 + n0 * 4) =
                make_float2(acc[mt][nt][0] + bv.x, acc[mt][nt][1] + bv.y);
            *(float2*)(smem + SM_STG + (r0 + 8) * 528 + n0 * 4) =
                make_float2(acc[mt][nt][2] + bv.x, acc[mt][nt][3] + bv.y);
        }
}

template <bool EDGE>
__global__ void __launch_bounds__(256, 2) mlp_kernel(
    const float* __restrict__ nf, const float* __restrict__ ef,
    const int* __restrict__ snd, const int* __restrict__ rcv,
    const float* __restrict__ b1, const float* __restrict__ b2, const float* __restrict__ b3,
    const float* __restrict__ gamma, const float* __restrict__ beta,
    float* __restrict__ out) {
    extern __shared__ char smem[];
    const uint32_t sb = (uint32_t)__cvta_generic_to_shared(smem);
    const int tid = threadIdx.x, lane = tid & 31, wid = tid >> 5;
    const int wm = wid >> 2, wn = wid & 3;
    const size_t base = (size_t)blockIdx.x * 64;
    const size_t LIM = EDGE ? NE : NN;

    int* sidx = (int*)(smem + SM_IDXS);
    int* ridx = (int*)(smem + SM_IDXR);
    if (EDGE && tid < 128) {
        size_t ge = base + (tid & 63);
        int v = (ge < NE) ? ((tid < 64) ? snd[ge] : rcv[ge]) : 0;
        if (tid < 64) sidx[tid] = v; else ridx[tid - 64] = v;
    }
    __syncthreads();

    const int grow = tid >> 2, q = tid & 3;   // gather mapping: 4 threads/row, 8 floats each

    float4 pre0, pre1;                        // prefetched gather regs (chunk g+1)
    auto ldg_chunk = [&](int g) {
        const float* src = nf;
        bool zero = false;
        size_t ge = base + grow;
        int seg = g >> 2, col0 = (g & 3) * 32;
        if (EDGE) {
            if (seg == 0)      src = nf + (size_t)sidx[grow] * D + col0;
            else if (seg == 1) src = nf + (size_t)ridx[grow] * D + col0;
            else               src = ef + ge * D + col0;
        } else {
            zero = (ge >= NN);
            src = (seg == 0 ? nf : g_agg) + (zero ? 0 : ge * D) + col0;
        }
        pre0 = zero ? make_float4(0.f, 0.f, 0.f, 0.f) : *(const float4*)(src + q * 8);
        pre1 = zero ? make_float4(0.f, 0.f, 0.f, 0.f) : *(const float4*)(src + q * 8 + 4);
    };
    auto sts_chunk = [&](int buf) {
        uint2 hi, lo;
        uint32_t off = XOFF(buf) + (uint32_t)grow * XSTR + (uint32_t)q * 16;
        split_pack4(pre0, hi, lo);
        *(uint2*)(smem + off) = hi;
        *(uint2*)(smem + off + 5120u) = lo;
        split_pack4(pre1, hi, lo);
        *(uint2*)(smem + off + 8u) = hi;
        *(uint2*)(smem + off + 5120u + 8u) = lo;
    };

    const int L1 = EDGE ? 12 : 8;       // 32-k chunks in layer 1
    const int NCH = L1 + 8;             // + 4 (L2) + 4 (L3)
    const int WR0 = EDGE ? 0 : 640;

    float acc[2][4][4];
#pragma unroll
    for (int mt = 0; mt < 2; mt++)
#pragma unroll
        for (int nt = 0; nt < 4; nt++)
#pragma unroll
            for (int i = 0; i < 4; i++) acc[mt][nt][i] = 0.f;

    ldg_chunk(0);                       // prefetch chunk 0

    for (int g = 0; g < NCH; g++) {
        const int buf = g & 1;
        __syncthreads();   // buffer buf free (gemm g-2 done); h/epi writes ordered
        if (g < L1) sts_chunk(buf);            // convert + STS chunk g (from prefetch regs)
        if (g + 1 < L1) ldg_chunk(g + 1);      // issue next gather; hidden behind gemm(g)
        if (g == 0) stage_w(sb, WOFF(0), WR0, tid);
        if (g + 1 < NCH) {
            stage_w(sb, WOFF(buf ^ 1), WR0 + (g + 1) * 32, tid);
            cp_wait<1>();
        } else {
            cp_wait<0>();
        }
        __syncthreads();

        uint32_t a_off, alo_rel, astr, kbase;
        if (g < L1) { a_off = XOFF(buf); alo_rel = 5120u; astr = XSTR; kbase = 0; }
        else { a_off = SM_H; alo_rel = 17408u; astr = 272u; kbase = (uint32_t)((g - L1) & 3) * 32u; }
        gemm_chunk(sb, a_off, alo_rel, astr, kbase, WOFF(buf), lane, wm, wn, acc);

        if (g == L1 - 1 || g == L1 + 3) {
            __syncthreads();   // all reads of h complete before it is overwritten
            epi_relu_split(acc, (g == L1 - 1) ? b1 : b2, smem, lane, wm, wn);
#pragma unroll
            for (int mt = 0; mt < 2; mt++)
#pragma unroll
                for (int nt = 0; nt < 4; nt++)
#pragma unroll
                    for (int i = 0; i < 4; i++) acc[mt][nt][i] = 0.f;
        }
    }
    __syncthreads();
    epi_f32(acc, b3, smem, lane, wm, wn);   // staging aliases dead stream buffers
    __syncthreads();

    // LN + residual (+ scatter for edges)
    const int ccg = tid & 15, ecg = tid >> 4;
    float4 g0 = *(const float4*)(gamma + ccg * 8), g1 = *(const float4*)(gamma + ccg * 8 + 4);
    float4 t0 = *(const float4*)(beta + ccg * 8),  t1 = *(const float4*)(beta + ccg * 8 + 4);
    float gv[8] = {g0.x, g0.y, g0.z, g0.w, g1.x, g1.y, g1.z, g1.w};
    float bv[8] = {t0.x, t0.y, t0.z, t0.w, t1.x, t1.y, t1.z, t1.w};
#pragma unroll
    for (int ei = 0; ei < 4; ei++) {
        int el = ecg * 4 + ei;
        size_t ge = base + el;
        float4 p0 = *(float4*)(smem + SM_STG + (uint32_t)el * 528 + ccg * 32);
        float4 p1 = *(float4*)(smem + SM_STG + (uint32_t)el * 528 + ccg * 32 + 16);
        float v[8] = {p0.x, p0.y, p0.z, p0.w, p1.x, p1.y, p1.z, p1.w};
        float s = 0.f, s2 = 0.f;
#pragma unroll
        for (int c = 0; c < 8; c++) { s += v[c]; s2 += v[c] * v[c]; }
#pragma unroll
        for (int m = 8; m >= 1; m >>= 1) {
            s  += __shfl_xor_sync(0xffffffffu, s, m);
            s2 += __shfl_xor_sync(0xffffffffu, s2, m);
        }
        if (ge >= LIM) continue;
        float mu = s * (1.f / D), var = s2 * (1.f / D) - mu * mu;
        float rstd = rsqrtf(fmaxf(var, 0.f) + 1e-5f);
        float nrm[8];
#pragma unroll
        for (int c = 0; c < 8; c++) nrm[c] = (v[c] - mu) * rstd * gv[c] + bv[c];
        if (EDGE) {
            float* ap = g_agg + (size_t)ridx[el] * D + ccg * 8;
            asm volatile("red.global.add.v4.f32 [%0], {%1,%2,%3,%4};" ::
                         "l"(ap), "f"(nrm[0]), "f"(nrm[1]), "f"(nrm[2]), "f"(nrm[3]) : "memory");
            asm volatile("red.global.add.v4.f32 [%0], {%1,%2,%3,%4};" ::
                         "l"(ap + 4), "f"(nrm[4]), "f"(nrm[5]), "f"(nrm[6]), "f"(nrm[7]) : "memory");
        }
        const float* res = (EDGE ? ef : nf) + ge * D + ccg * 8;
        float4 e0 = *(const float4*)res, e1 = *(const float4*)(res + 4);
        float* op = out + ge * D + ccg * 8;
        *(float4*)op       = make_float4(nrm[0] + e0.x, nrm[1] + e0.y, nrm[2] + e0.z, nrm[3] + e0.w);
        *(float4*)(op + 4) = make_float4(nrm[4] + e1.x, nrm[5] + e1.y, nrm[6] + e1.z, nrm[7] + e1.w);
    }
}

extern "C" void kernel_launch(void* const* d_in, const int* in_sizes, int n_in,
                              void* d_out, int out_size) {
    const float* nf  = (const float*)d_in[0];
    const float* ef  = (const float*)d_in[1];
    const int*   snd = (const int*)d_in[2];
    const int*   rcv = (const int*)d_in[3];
    const float* ew1 = (const float*)d_in[4];
    const float* eb1 = (const float*)d_in[5];
    const float* ew2 = (const float*)d_in[6];
    const float* eb2 = (const float*)d_in[7];
    const float* ew3 = (const float*)d_in[8];
    const float* eb3 = (const float*)d_in[9];
    const float* eg  = (const float*)d_in[10];
    const float* ebt = (const float*)d_in[11];
    const float* nw1 = (const float*)d_in[12];
    const float* nb1 = (const float*)d_in[13];
    const float* nw2 = (const float*)d_in[14];
    const float* nb2 = (const float*)d_in[15];
    const float* nw3 = (const float*)d_in[16];
    const float* nb3 = (const float*)d_in[17];
    const float* ng  = (const float*)d_in[18];
    const float* nbt = (const float*)d_in[19];

    float* out_n = (float*)d_out;
    float* out_e = out_n + (size_t)NN * D;

    cudaFuncSetAttribute(mlp_kernel<true>,  cudaFuncAttributeMaxDynamicSharedMemorySize, SMEM_TOTAL);
    cudaFuncSetAttribute(mlp_kernel<false>, cudaFuncAttributeMaxDynamicSharedMemorySize, SMEM_TOTAL);

    prep_weights<<<612, 256>>>(ew1, ew2, ew3, nw1, nw2, nw3);
    zero_agg_kernel<<<NN * D / 4 / 256, 256>>>();
    mlp_kernel<true><<<NE / 64, 256, SMEM_TOTAL>>>(nf, ef, snd, rcv,
                                                   eb1, eb2, eb3, eg, ebt, out_e);
    mlp_kernel<false><<<(NN + 63) / 64, 256, SMEM_TOTAL>>>(nf, ef, snd, rcv,
                                                           nb1, nb2, nb3, ng, nbt, out_n);
}

// round 9
// speedup vs baseline: 6.9937x; 1.0693x over previous
#include <cuda_runtime.h>
#include <cuda_fp16.h>
#include <cstdint>

#define NN 100000
#define NE 600000
#define D  128
#define WPAD 136            // weight row width (272B rows)

// smem layout (bytes): two stream buffers [X(10240: hi 5120|lo 5120) + W(8704)]
// then h (hi only, 17408). LN staging (64*528=33792) aliases stream buffers.
#define XSTR   80u
#define BUFSZ  18944u
#define XOFF(b) ((uint32_t)(b) * BUFSZ)
#define WOFF(b) ((uint32_t)(b) * BUFSZ + 10240u)
#define SM_H    37888u
#define SM_STG  0u
#define SM_IDXS 55296u
#define SM_IDXR 55552u
#define SMEM_TOTAL 55808

__device__ float g_agg[(size_t)NN * D];
// stacked fp16 weights (rows x 272B): [0,384) ew1 | [384,512) ew2 | [512,640) ew3 |
// [640,896) nw1[0:256] | [896,1024) nw2 | [1024,1152) nw3
__device__ __half g_w[1152 * WPAD];

__global__ void zero_agg_kernel() {
    size_t i = (size_t)blockIdx.x * blockDim.x + threadIdx.x;
    ((float4*)g_agg)[i] = make_float4(0.f, 0.f, 0.f, 0.f);
}

__global__ void prep_weights(const float* __restrict__ ew1, const float* __restrict__ ew2,
                             const float* __restrict__ ew3, const float* __restrict__ nw1,
                             const float* __restrict__ nw2, const float* __restrict__ nw3) {
    int idx = blockIdx.x * 256 + threadIdx.x;
    if (idx >= 1152 * WPAD) return;
    int r = idx / WPAD, c = idx % WPAD;
    float v = 0.f;
    if (c < 128) {
        if (r < 384)       v = ew1[r * 128 + c];
        else if (r < 512)  v = ew2[(r - 384) * 128 + c];
        else if (r < 640)  v = ew3[(r - 512) * 128 + c];
        else if (r < 896)  v = nw1[(r - 640) * 128 + c];
        else if (r < 1024) v = nw2[(r - 896) * 128 + c];
        else               v = nw3[(r - 1024) * 128 + c];
    }
    g_w[idx] = __float2half_rn(v);
}

// ---------------- helpers ----------------
__device__ __forceinline__ void mma16816(float* c, const uint32_t* a, const uint32_t* b) {
    asm volatile(
        "mma.sync.aligned.m16n8k16.row.col.f32.f16.f16.f32 "
        "{%0,%1,%2,%3}, {%4,%5,%6,%7}, {%8,%9}, {%0,%1,%2,%3};"
        : "+f"(c[0]), "+f"(c[1]), "+f"(c[2]), "+f"(c[3])
        : "r"(a[0]), "r"(a[1]), "r"(a[2]), "r"(a[3]), "r"(b[0]), "r"(b[1]));
}
__device__ __forceinline__ void ldm_a(uint32_t* r, uint32_t addr) {
    asm volatile("ldmatrix.sync.aligned.m8n8.x4.shared.b16 {%0,%1,%2,%3}, [%4];"
                 : "=r"(r[0]), "=r"(r[1]), "=r"(r[2]), "=r"(r[3]) : "r"(addr));
}
__device__ __forceinline__ void ldm_bt4(uint32_t* r, uint32_t addr) {
    asm volatile("ldmatrix.sync.aligned.m8n8.x4.trans.shared.b16 {%0,%1,%2,%3}, [%4];"
                 : "=r"(r[0]), "=r"(r[1]), "=r"(r[2]), "=r"(r[3]) : "r"(addr));
}
__device__ __forceinline__ void cp16(uint32_t s, const void* g) {
    asm volatile("cp.async.cg.shared.global [%0], [%1], 16;" :: "r"(s), "l"(g));
}
#define CP_COMMIT() asm volatile("cp.async.commit_group;")
template <int N>
__device__ __forceinline__ void cp_wait() { asm volatile("cp.async.wait_group %0;" :: "n"(N)); }

__device__ __forceinline__ uint32_t hpack(__half a, __half b) {
    __half2 t = __halves2half2(a, b);
    return *reinterpret_cast<uint32_t*>(&t);
}
__device__ __forceinline__ void split_pack4(float4 v, uint2& hi, uint2& lo) {
    __half h0 = __float2half_rn(v.x), h1 = __float2half_rn(v.y);
    __half h2 = __float2half_rn(v.z), h3 = __float2half_rn(v.w);
    hi.x = hpack(h0, h1); hi.y = hpack(h2, h3);
    lo.x = hpack(__float2half_rn(v.x - __half2float(h0)),
                 __float2half_rn(v.y - __half2float(h1)));
    lo.y = hpack(__float2half_rn(v.z - __half2float(h2)),
                 __float2half_rn(v.w - __half2float(h3)));
}

// stage one 32-row fp16 weight chunk (8704B) via cp.async
__device__ __forceinline__ void stage_w(uint32_t sb, uint32_t woff, int wrow, int tid) {
    const char* sw = (const char*)(g_w + (size_t)wrow * WPAD);
#pragma unroll
    for (int i = 0; i < 3; i++) {
        int j = tid + i * 256;
        if (j < 544) cp16(sb + woff + (uint32_t)j * 16, sw + j * 16);
    }
    CP_COMMIT();
}

// compute one 32-k chunk: acc[2][4][4] += A[64 x 32] * W[32 x 128]
// NP = A planes (2: hi+lo error-compensated, 1: hi only).
template <int NP>
__device__ __forceinline__ void gemm_chunk(uint32_t sb, uint32_t a_off, uint32_t alo_rel,
                                           uint32_t astr, uint32_t kbase, uint32_t w_off,
                                           int lane, int wm, int wn, float acc[2][4][4]) {
    uint32_t bw[4][4];
    uint32_t brow = (uint32_t)lane * 272u;
#pragma unroll
    for (int nt = 0; nt < 4; nt++) {
        uint32_t nb = (uint32_t)(wn * 32 + nt * 8) * 2;
        ldm_bt4(bw[nt], sb + w_off + brow + nb);
    }
#pragma unroll
    for (int ks = 0; ks < 2; ks++) {
        uint32_t ah[2][4], al[2][4];
        uint32_t colb = (kbase + (uint32_t)ks * 16 + (uint32_t)((lane >> 4) << 3)) * 2;
#pragma unroll
        for (int mt = 0; mt < 2; mt++) {
            uint32_t row = (uint32_t)(wm * 32 + mt * 16 + (lane & 15));
            ldm_a(ah[mt], sb + a_off + row * astr + colb);
            if (NP == 2) ldm_a(al[mt], sb + a_off + alo_rel + row * astr + colb);
        }
#pragma unroll
        for (int mt = 0; mt < 2; mt++)
#pragma unroll
            for (int nt = 0; nt < 4; nt++) {
                mma16816(acc[mt][nt], ah[mt], &bw[nt][ks * 2]);
                if (NP == 2) mma16816(acc[mt][nt], al[mt], &bw[nt][ks * 2]);
            }
    }
}

// bias + relu -> fp16 h image, hi plane only (stride 272B)
__device__ __forceinline__ void epi_relu(float acc[2][4][4], const float* __restrict__ bias,
                                         char* smem, int lane, int wm, int wn) {
#pragma unroll
    for (int mt = 0; mt < 2; mt++)
#pragma unroll
        for (int nt = 0; nt < 4; nt++) {
            int n0 = wn * 32 + nt * 8 + (lane & 3) * 2;
            float2 bv = *(const float2*)(bias + n0);
            int r0 = wm * 32 + mt * 16 + (lane >> 2);
            float v0 = fmaxf(acc[mt][nt][0] + bv.x, 0.f);
            float v1 = fmaxf(acc[mt][nt][1] + bv.y, 0.f);
            float v2 = fmaxf(acc[mt][nt][2] + bv.x, 0.f);
            float v3 = fmaxf(acc[mt][nt][3] + bv.y, 0.f);
            *(uint32_t*)(smem + SM_H + r0 * 272 + n0 * 2) =
                hpack(__float2half_rn(v0), __float2half_rn(v1));
            *(uint32_t*)(smem + SM_H + (r0 + 8) * 272 + n0 * 2) =
                hpack(__float2half_rn(v2), __float2half_rn(v3));
        }
}

// layer3: bias only -> fp32 staging (stride 528B)
__device__ __forceinline__ void epi_f32(float acc[2][4][4], const float* __restrict__ bias,
                                        char* smem, int lane, int wm, int wn) {
#pragma unroll
    for (int mt = 0; mt < 2; mt++)
#pragma unroll
        for (int nt = 0; nt < 4; nt++) {
            int n0 = wn * 32 + nt * 8 + (lane & 3) * 2;
            float2 bv = *(const float2*)(bias + n0);
            int r0 = wm * 32 + mt * 16 + (lane >> 2);
            *(float2*)(smem + SM_STG + r0 * 528 + n0 * 4) =
                make_float2(acc[mt][nt][0] + bv.x, acc[mt][nt][1] + bv.y);
            *(float2*)(smem + SM_STG + (r0 + 8) * 528 + n0 * 4) =
                make_float2(acc[mt][nt][2] + bv.x, acc[mt][nt][3] + bv.y);
        }
}

template <bool EDGE>
__global__ void __launch_bounds__(256, 2) mlp_kernel(
    const float* __restrict__ nf, const float* __restrict__ ef,
    const int* __restrict__ snd, const int* __restrict__ rcv,
    const float* __restrict__ b1, const float* __restrict__ b2, const float* __restrict__ b3,
    const float* __restrict__ gamma, const float* __restrict__ beta,
    float* __restrict__ out) {
    extern __shared__ char smem[];
    const uint32_t sb = (uint32_t)__cvta_generic_to_shared(smem);
    const int tid = threadIdx.x, lane = tid & 31, wid = tid >> 5;
    const int wm = wid >> 2, wn = wid & 3;
    const size_t base = (size_t)blockIdx.x * 64;
    const size_t LIM = EDGE ? NE : NN;

    int* sidx = (int*)(smem + SM_IDXS);
    int* ridx = (int*)(smem + SM_IDXR);
    if (EDGE && tid < 128) {
        size_t ge = base + (tid & 63);
        int v = (ge < NE) ? ((tid < 64) ? snd[ge] : rcv[ge]) : 0;
        if (tid < 64) sidx[tid] = v; else ridx[tid - 64] = v;
    }
    __syncthreads();

    const int grow = tid >> 2, q = tid & 3;   // gather mapping: 4 threads/row, 8 floats each

    float4 pre0, pre1;                        // prefetched gather regs (chunk g+1)
    auto ldg_chunk = [&](int g) {
        const float* src = nf;
        bool zero = false;
        size_t ge = base + grow;
        int seg = g >> 2, col0 = (g & 3) * 32;
        if (EDGE) {
            if (seg == 0)      src = nf + (size_t)sidx[grow] * D + col0;
            else if (seg == 1) src = nf + (size_t)ridx[grow] * D + col0;
            else               src = ef + ge * D + col0;
        } else {
            zero = (ge >= NN);
            src = (seg == 0 ? nf : g_agg) + (zero ? 0 : ge * D) + col0;
        }
        pre0 = zero ? make_float4(0.f, 0.f, 0.f, 0.f) : *(const float4*)(src + q * 8);
        pre1 = zero ? make_float4(0.f, 0.f, 0.f, 0.f) : *(const float4*)(src + q * 8 + 4);
    };
    auto sts_chunk = [&](int buf) {
        uint2 hi, lo;
        uint32_t off = XOFF(buf) + (uint32_t)grow * XSTR + (uint32_t)q * 16;
        split_pack4(pre0, hi, lo);
        *(uint2*)(smem + off) = hi;
        *(uint2*)(smem + off + 5120u) = lo;
        split_pack4(pre1, hi, lo);
        *(uint2*)(smem + off + 8u) = hi;
        *(uint2*)(smem + off + 5120u + 8u) = lo;
    };

    const int L1 = EDGE ? 12 : 8;       // 32-k chunks in layer 1
    const int NCH = L1 + 8;             // + 4 (L2) + 4 (L3)
    const int WR0 = EDGE ? 0 : 640;

    float acc[2][4][4];
#pragma unroll
    for (int mt = 0; mt < 2; mt++)
#pragma unroll
        for (int nt = 0; nt < 4; nt++)
#pragma unroll
            for (int i = 0; i < 4; i++) acc[mt][nt][i] = 0.f;

    ldg_chunk(0);                       // prefetch chunk 0

    for (int g = 0; g < NCH; g++) {
        const int buf = g & 1;
        __syncthreads();   // buffer buf free (gemm g-2 done); h/epi writes ordered
        if (g < L1) sts_chunk(buf);            // convert + STS chunk g (from prefetch regs)
        if (g + 1 < L1) ldg_chunk(g + 1);      // issue next gather; hidden behind gemm(g)
        if (g == 0) stage_w(sb, WOFF(0), WR0, tid);
        if (g + 1 < NCH) {
            stage_w(sb, WOFF(buf ^ 1), WR0 + (g + 1) * 32, tid);
            cp_wait<1>();
        } else {
            cp_wait<0>();
        }
        __syncthreads();

        if (g < L1) {
            gemm_chunk<2>(sb, XOFF(buf), 5120u, XSTR, 0u, WOFF(buf), lane, wm, wn, acc);
        } else {
            gemm_chunk<1>(sb, SM_H, 0u, 272u, (uint32_t)((g - L1) & 3) * 32u,
                          WOFF(buf), lane, wm, wn, acc);
        }

        if (g == L1 - 1 || g == L1 + 3) {
            __syncthreads();   // all reads of h complete before it is overwritten
            epi_relu(acc, (g == L1 - 1) ? b1 : b2, smem, lane, wm, wn);
#pragma unroll
            for (int mt = 0; mt < 2; mt++)
#pragma unroll
                for (int nt = 0; nt < 4; nt++)
#pragma unroll
                    for (int i = 0; i < 4; i++) acc[mt][nt][i] = 0.f;
        }
    }
    __syncthreads();
    epi_f32(acc, b3, smem, lane, wm, wn);   // staging aliases dead stream buffers
    __syncthreads();

    // LN + residual (+ scatter for edges)
    const int ccg = tid & 15, ecg = tid >> 4;
    float4 g0 = *(const float4*)(gamma + ccg * 8), g1 = *(const float4*)(gamma + ccg * 8 + 4);
    float4 t0 = *(const float4*)(beta + ccg * 8),  t1 = *(const float4*)(beta + ccg * 8 + 4);
    float gv[8] = {g0.x, g0.y, g0.z, g0.w, g1.x, g1.y, g1.z, g1.w};
    float bv[8] = {t0.x, t0.y, t0.z, t0.w, t1.x, t1.y, t1.z, t1.w};
#pragma unroll
    for (int ei = 0; ei < 4; ei++) {
        int el = ecg * 4 + ei;
        size_t ge = base + el;
        float4 p0 = *(float4*)(smem + SM_STG + (uint32_t)el * 528 + ccg * 32);
        float4 p1 = *(float4*)(smem + SM_STG + (uint32_t)el * 528 + ccg * 32 + 16);
        float v[8] = {p0.x, p0.y, p0.z, p0.w, p1.x, p1.y, p1.z, p1.w};
        float s = 0.f, s2 = 0.f;
#pragma unroll
        for (int c = 0; c < 8; c++) { s += v[c]; s2 += v[c] * v[c]; }
#pragma unroll
        for (int m = 8; m >= 1; m >>= 1) {
            s  += __shfl_xor_sync(0xffffffffu, s, m);
            s2 += __shfl_xor_sync(0xffffffffu, s2, m);
        }
        if (ge >= LIM) continue;
        float mu = s * (1.f / D), var = s2 * (1.f / D) - mu * mu;
        float rstd = rsqrtf(fmaxf(var, 0.f) + 1e-5f);
        float nrm[8];
#pragma unroll
        for (int c = 0; c < 8; c++) nrm[c] = (v[c] - mu) * rstd * gv[c] + bv[c];
        if (EDGE) {
            float* ap = g_agg + (size_t)ridx[el] * D + ccg * 8;
            asm volatile("red.global.add.v4.f32 [%0], {%1,%2,%3,%4};" ::
                         "l"(ap), "f"(nrm[0]), "f"(nrm[1]), "f"(nrm[2]), "f"(nrm[3]) : "memory");
            asm volatile("red.global.add.v4.f32 [%0], {%1,%2,%3,%4};" ::
                         "l"(ap + 4), "f"(nrm[4]), "f"(nrm[5]), "f"(nrm[6]), "f"(nrm[7]) : "memory");
        }
        const float* res = (EDGE ? ef : nf) + ge * D + ccg * 8;
        float4 e0 = *(const float4*)res, e1 = *(const float4*)(res + 4);
        float* op = out + ge * D + ccg * 8;
        *(float4*)op       = make_float4(nrm[0] + e0.x, nrm[1] + e0.y, nrm[2] + e0.z, nrm[3] + e0.w);
        *(float4*)(op + 4) = make_float4(nrm[4] + e1.x, nrm[5] + e1.y, nrm[6] + e1.z, nrm[7] + e1.w);
    }
}

extern "C" void kernel_launch(void* const* d_in, const int* in_sizes, int n_in,
                              void* d_out, int out_size) {
    const float* nf  = (const float*)d_in[0];
    const float* ef  = (const float*)d_in[1];
    const int*   snd = (const int*)d_in[2];
    const int*   rcv = (const int*)d_in[3];
    const float* ew1 = (const float*)d_in[4];
    const float* eb1 = (const float*)d_in[5];
    const float* ew2 = (const float*)d_in[6];
    const float* eb2 = (const float*)d_in[7];
    const float* ew3 = (const float*)d_in[8];
    const float* eb3 = (const float*)d_in[9];
    const float* eg  = (const float*)d_in[10];
    const float* ebt = (const float*)d_in[11];
    const float* nw1 = (const float*)d_in[12];
    const float* nb1 = (const float*)d_in[13];
    const float* nw2 = (const float*)d_in[14];
    const float* nb2 = (const float*)d_in[15];
    const float* nw3 = (const float*)d_in[16];
    const float* nb3 = (const float*)d_in[17];
    const float* ng  = (const float*)d_in[18];
    const float* nbt = (const float*)d_in[19];

    float* out_n = (float*)d_out;
    float* out_e = out_n + (size_t)NN * D;

    cudaFuncSetAttribute(mlp_kernel<true>,  cudaFuncAttributeMaxDynamicSharedMemorySize, SMEM_TOTAL);
    cudaFuncSetAttribute(mlp_kernel<false>, cudaFuncAttributeMaxDynamicSharedMemorySize, SMEM_TOTAL);

    prep_weights<<<612, 256>>>(ew1, ew2, ew3, nw1, nw2, nw3);
    zero_agg_kernel<<<NN * D / 4 / 256, 256>>>();
    mlp_kernel<true><<<NE / 64, 256, SMEM_TOTAL>>>(nf, ef, snd, rcv,
                                                   eb1, eb2, eb3, eg, ebt, out_e);
    mlp_kernel<false><<<(NN + 63) / 64, 256, SMEM_TOTAL>>>(nf, ef, snd, rcv,
                                                           nb1, nb2, nb3, ng, nbt, out_n);
}

// round 10
// speedup vs baseline: 9.2140x; 1.3175x over previous
#include <cuda_runtime.h>
#include <cuda_fp16.h>
#include <cstdint>

#define NN 100000
#define NE 600000
#define D  128
#define WPAD 136            // weight row width (272B rows)

// smem layout (bytes): two stream buffers [X(5120) + W(8704)] = 13824 each,
// then h (17408). LN staging (64*528=33792) aliases buffers+h (dead after layer3).
#define XSTR   80u
#define BUFSZ  13824u
#define XOFF(b) ((uint32_t)(b) * BUFSZ)
#define WOFF(b) ((uint32_t)(b) * BUFSZ + 5120u)
#define SM_H    27648u
#define SM_STG  0u
#define SM_IDXS 45056u
#define SM_IDXR 45312u
#define SMEM_TOTAL 45568

__device__ float g_agg[(size_t)NN * D];
// stacked fp16 weights (rows x 272B): [0,384) ew1 | [384,512) ew2 | [512,640) ew3 |
// [640,896) nw1[0:256] | [896,1024) nw2 | [1024,1152) nw3
__device__ __half g_w[1152 * WPAD];

__global__ void zero_agg_kernel() {
    size_t i = (size_t)blockIdx.x * blockDim.x + threadIdx.x;
    ((float4*)g_agg)[i] = make_float4(0.f, 0.f, 0.f, 0.f);
}

__global__ void prep_weights(const float* __restrict__ ew1, const float* __restrict__ ew2,
                             const float* __restrict__ ew3, const float* __restrict__ nw1,
                             const float* __restrict__ nw2, const float* __restrict__ nw3) {
    int idx = blockIdx.x * 256 + threadIdx.x;
    if (idx >= 1152 * WPAD) return;
    int r = idx / WPAD, c = idx % WPAD;
    float v = 0.f;
    if (c < 128) {
        if (r < 384)       v = ew1[r * 128 + c];
        else if (r < 512)  v = ew2[(r - 384) * 128 + c];
        else if (r < 640)  v = ew3[(r - 512) * 128 + c];
        else if (r < 896)  v = nw1[(r - 640) * 128 + c];
        else if (r < 1024) v = nw2[(r - 896) * 128 + c];
        else               v = nw3[(r - 1024) * 128 + c];
    }
    g_w[idx] = __float2half_rn(v);
}

// ---------------- helpers ----------------
__device__ __forceinline__ void mma16816(float* c, const uint32_t* a, const uint32_t* b) {
    asm volatile(
        "mma.sync.aligned.m16n8k16.row.col.f32.f16.f16.f32 "
        "{%0,%1,%2,%3}, {%4,%5,%6,%7}, {%8,%9}, {%0,%1,%2,%3};"
        : "+f"(c[0]), "+f"(c[1]), "+f"(c[2]), "+f"(c[3])
        : "r"(a[0]), "r"(a[1]), "r"(a[2]), "r"(a[3]), "r"(b[0]), "r"(b[1]));
}
__device__ __forceinline__ void ldm_a(uint32_t* r, uint32_t addr) {
    asm volatile("ldmatrix.sync.aligned.m8n8.x4.shared.b16 {%0,%1,%2,%3}, [%4];"
                 : "=r"(r[0]), "=r"(r[1]), "=r"(r[2]), "=r"(r[3]) : "r"(addr));
}
__device__ __forceinline__ void ldm_bt4(uint32_t* r, uint32_t addr) {
    asm volatile("ldmatrix.sync.aligned.m8n8.x4.trans.shared.b16 {%0,%1,%2,%3}, [%4];"
                 : "=r"(r[0]), "=r"(r[1]), "=r"(r[2]), "=r"(r[3]) : "r"(addr));
}
__device__ __forceinline__ void cp16(uint32_t s, const void* g) {
    asm volatile("cp.async.cg.shared.global [%0], [%1], 16;" :: "r"(s), "l"(g));
}
#define CP_COMMIT() asm volatile("cp.async.commit_group;")
template <int N>
__device__ __forceinline__ void cp_wait() { asm volatile("cp.async.wait_group %0;" :: "n"(N)); }

__device__ __forceinline__ uint32_t hpack(__half a, __half b) {
    __half2 t = __halves2half2(a, b);
    return *reinterpret_cast<uint32_t*>(&t);
}

// stage one 32-row fp16 weight chunk (8704B) via cp.async
__device__ __forceinline__ void stage_w(uint32_t sb, uint32_t woff, int wrow, int tid) {
    const char* sw = (const char*)(g_w + (size_t)wrow * WPAD);
#pragma unroll
    for (int i = 0; i < 3; i++) {
        int j = tid + i * 256;
        if (j < 544) cp16(sb + woff + (uint32_t)j * 16, sw + j * 16);
    }
    CP_COMMIT();
}

// compute one 32-k chunk: acc[2][4][4] += A[64 x 32] * W[32 x 128]  (single fp16 plane)
__device__ __forceinline__ void gemm_chunk(uint32_t sb, uint32_t a_off, uint32_t astr,
                                           uint32_t kbase, uint32_t w_off,
                                           int lane, int wm, int wn, float acc[2][4][4]) {
    uint32_t bw[4][4];
    uint32_t brow = (uint32_t)lane * 272u;
#pragma unroll
    for (int nt = 0; nt < 4; nt++) {
        uint32_t nb = (uint32_t)(wn * 32 + nt * 8) * 2;
        ldm_bt4(bw[nt], sb + w_off + brow + nb);
    }
#pragma unroll
    for (int ks = 0; ks < 2; ks++) {
        uint32_t ah[2][4];
        uint32_t colb = (kbase + (uint32_t)ks * 16 + (uint32_t)((lane >> 4) << 3)) * 2;
#pragma unroll
        for (int mt = 0; mt < 2; mt++) {
            uint32_t row = (uint32_t)(wm * 32 + mt * 16 + (lane & 15));
            ldm_a(ah[mt], sb + a_off + row * astr + colb);
        }
#pragma unroll
        for (int mt = 0; mt < 2; mt++)
#pragma unroll
            for (int nt = 0; nt < 4; nt++)
                mma16816(acc[mt][nt], ah[mt], &bw[nt][ks * 2]);
    }
}

// bias + relu -> fp16 h image (stride 272B)
__device__ __forceinline__ void epi_relu(float acc[2][4][4], const float* __restrict__ bias,
                                         char* smem, int lane, int wm, int wn) {
#pragma unroll
    for (int mt = 0; mt < 2; mt++)
#pragma unroll
        for (int nt = 0; nt < 4; nt++) {
            int n0 = wn * 32 + nt * 8 + (lane & 3) * 2;
            float2 bv = *(const float2*)(bias + n0);
            int r0 = wm * 32 + mt * 16 + (lane >> 2);
            float v0 = fmaxf(acc[mt][nt][0] + bv.x, 0.f);
            float v1 = fmaxf(acc[mt][nt][1] + bv.y, 0.f);
            float v2 = fmaxf(acc[mt][nt][2] + bv.x, 0.f);
            float v3 = fmaxf(acc[mt][nt][3] + bv.y, 0.f);
            *(uint32_t*)(smem + SM_H + r0 * 272 + n0 * 2) =
                hpack(__float2half_rn(v0), __float2half_rn(v1));
            *(uint32_t*)(smem + SM_H + (r0 + 8) * 272 + n0 * 2) =
                hpack(__float2half_rn(v2), __float2half_rn(v3));
        }
}

// layer3: bias only -> fp32 staging (stride 528B)
__device__ __forceinline__ void epi_f32(float acc[2][4][4], const float* __restrict__ bias,
                                        char* smem, int lane, int wm, int wn) {
#pragma unroll
    for (int mt = 0; mt < 2; mt++)
#pragma unroll
        for (int nt = 0; nt < 4; nt++) {
            int n0 = wn * 32 + nt * 8 + (lane & 3) * 2;
            float2 bv = *(const float2*)(bias + n0);
            int r0 = wm * 32 + mt * 16 + (lane >> 2);
            *(float2*)(smem + SM_STG + r0 * 528 + n0 * 4) =
                make_float2(acc[mt][nt][0] + bv.x, acc[mt][nt][1] + bv.y);
            *(float2*)(smem + SM_STG + (r0 + 8) * 528 + n0 * 4) =
                make_float2(acc[mt][nt][2] + bv.x, acc[mt][nt][3] + bv.y);
        }
}

template <bool EDGE>
__global__ void __launch_bounds__(256, 3) mlp_kernel(
    const float* __restrict__ nf, const float* __restrict__ ef,
    const int* __restrict__ snd, const int* __restrict__ rcv,
    const float* __restrict__ b1, const float* __restrict__ b2, const float* __restrict__ b3,
    const float* __restrict__ gamma, const float* __restrict__ beta,
    float* __restrict__ out) {
    extern __shared__ char smem[];
    const uint32_t sb = (uint32_t)__cvta_generic_to_shared(smem);
    const int tid = threadIdx.x, lane = tid & 31, wid = tid >> 5;
    const int wm = wid >> 2, wn = wid & 3;
    const size_t base = (size_t)blockIdx.x * 64;
    const size_t LIM = EDGE ? NE : NN;

    int* sidx = (int*)(smem + SM_IDXS);
    int* ridx = (int*)(smem + SM_IDXR);
    if (EDGE && tid < 128) {
        size_t ge = base + (tid & 63);
        int v = (ge < NE) ? ((tid < 64) ? snd[ge] : rcv[ge]) : 0;
        if (tid < 64) sidx[tid] = v; else ridx[tid - 64] = v;
    }
    __syncthreads();

    const int grow = tid >> 2, q = tid & 3;   // gather mapping: 4 threads/row, 8 floats each

    float4 pre0, pre1;                        // prefetched gather regs (chunk g+1)
    auto ldg_chunk = [&](int g) {
        const float* src = nf;
        bool zero = false;
        size_t ge = base + grow;
        int seg = g >> 2, col0 = (g & 3) * 32;
        if (EDGE) {
            if (seg == 0)      src = nf + (size_t)sidx[grow] * D + col0;
            else if (seg == 1) src = nf + (size_t)ridx[grow] * D + col0;
            else               src = ef + ge * D + col0;
        } else {
            zero = (ge >= NN);
            src = (seg == 0 ? nf : g_agg) + (zero ? 0 : ge * D) + col0;
        }
        pre0 = zero ? make_float4(0.f, 0.f, 0.f, 0.f) : *(const float4*)(src + q * 8);
        pre1 = zero ? make_float4(0.f, 0.f, 0.f, 0.f) : *(const float4*)(src + q * 8 + 4);
    };
    auto sts_chunk = [&](int buf) {
        uint4 h;
        h.x = hpack(__float2half_rn(pre0.x), __float2half_rn(pre0.y));
        h.y = hpack(__float2half_rn(pre0.z), __float2half_rn(pre0.w));
        h.z = hpack(__float2half_rn(pre1.x), __float2half_rn(pre1.y));
        h.w = hpack(__float2half_rn(pre1.z), __float2half_rn(pre1.w));
        *(uint4*)(smem + XOFF(buf) + (uint32_t)grow * XSTR + (uint32_t)q * 16) = h;
    };

    const int L1 = EDGE ? 12 : 8;       // 32-k chunks in layer 1
    const int NCH = L1 + 8;             // + 4 (L2) + 4 (L3)
    const int WR0 = EDGE ? 0 : 640;

    float acc[2][4][4];
#pragma unroll
    for (int mt = 0; mt < 2; mt++)
#pragma unroll
        for (int nt = 0; nt < 4; nt++)
#pragma unroll
            for (int i = 0; i < 4; i++) acc[mt][nt][i] = 0.f;

    ldg_chunk(0);                       // prefetch chunk 0

    for (int g = 0; g < NCH; g++) {
        const int buf = g & 1;
        __syncthreads();   // buffer buf free (gemm g-2 done); h/epi writes ordered
        if (g < L1) sts_chunk(buf);            // convert + STS chunk g (from prefetch regs)
        if (g + 1 < L1) ldg_chunk(g + 1);      // issue next gather; hidden behind gemm(g)
        if (g == 0) stage_w(sb, WOFF(0), WR0, tid);
        if (g + 1 < NCH) {
            stage_w(sb, WOFF(buf ^ 1), WR0 + (g + 1) * 32, tid);
            cp_wait<1>();
        } else {
            cp_wait<0>();
        }
        __syncthreads();

        if (g < L1) {
            gemm_chunk(sb, XOFF(buf), XSTR, 0u, WOFF(buf), lane, wm, wn, acc);
        } else {
            gemm_chunk(sb, SM_H, 272u, (uint32_t)((g - L1) & 3) * 32u,
                       WOFF(buf), lane, wm, wn, acc);
        }

        if (g == L1 - 1 || g == L1 + 3) {
            __syncthreads();   // all reads of h complete before it is overwritten
            epi_relu(acc, (g == L1 - 1) ? b1 : b2, smem, lane, wm, wn);
#pragma unroll
            for (int mt = 0; mt < 2; mt++)
#pragma unroll
                for (int nt = 0; nt < 4; nt++)
#pragma unroll
                    for (int i = 0; i < 4; i++) acc[mt][nt][i] = 0.f;
        }
    }
    __syncthreads();
    epi_f32(acc, b3, smem, lane, wm, wn);   // staging aliases dead buffers + h
    __syncthreads();

    // LN + residual (+ scatter for edges)
    const int ccg = tid & 15, ecg = tid >> 4;
    float4 g0 = *(const float4*)(gamma + ccg * 8), g1 = *(const float4*)(gamma + ccg * 8 + 4);
    float4 t0 = *(const float4*)(beta + ccg * 8),  t1 = *(const float4*)(beta + ccg * 8 + 4);
    float gv[8] = {g0.x, g0.y, g0.z, g0.w, g1.x, g1.y, g1.z, g1.w};
    float bv[8] = {t0.x, t0.y, t0.z, t0.w, t1.x, t1.y, t1.z, t1.w};
#pragma unroll
    for (int ei = 0; ei < 4; ei++) {
        int el = ecg * 4 + ei;
        size_t ge = base + el;
        float4 p0 = *(float4*)(smem + SM_STG + (uint32_t)el * 528 + ccg * 32);
        float4 p1 = *(float4*)(smem + SM_STG + (uint32_t)el * 528 + ccg * 32 + 16);
        float v[8] = {p0.x, p0.y, p0.z, p0.w, p1.x, p1.y, p1.z, p1.w};
        float s = 0.f, s2 = 0.f;
#pragma unroll
        for (int c = 0; c < 8; c++) { s += v[c]; s2 += v[c] * v[c]; }
#pragma unroll
        for (int m = 8; m >= 1; m >>= 1) {
            s  += __shfl_xor_sync(0xffffffffu, s, m);
            s2 += __shfl_xor_sync(0xffffffffu, s2, m);
        }
        if (ge >= LIM) continue;
        float mu = s * (1.f / D), var = s2 * (1.f / D) - mu * mu;
        float rstd = rsqrtf(fmaxf(var, 0.f) + 1e-5f);
        float nrm[8];
#pragma unroll
        for (int c = 0; c < 8; c++) nrm[c] = (v[c] - mu) * rstd * gv[c] + bv[c];
        if (EDGE) {
            float* ap = g_agg + (size_t)ridx[el] * D + ccg * 8;
            asm volatile("red.global.add.v4.f32 [%0], {%1,%2,%3,%4};" ::
                         "l"(ap), "f"(nrm[0]), "f"(nrm[1]), "f"(nrm[2]), "f"(nrm[3]) : "memory");
            asm volatile("red.global.add.v4.f32 [%0], {%1,%2,%3,%4};" ::
                         "l"(ap + 4), "f"(nrm[4]), "f"(nrm[5]), "f"(nrm[6]), "f"(nrm[7]) : "memory");
        }
        const float* res = (EDGE ? ef : nf) + ge * D + ccg * 8;
        float4 e0 = *(const float4*)res, e1 = *(const float4*)(res + 4);
        float* op = out + ge * D + ccg * 8;
        *(float4*)op       = make_float4(nrm[0] + e0.x, nrm[1] + e0.y, nrm[2] + e0.z, nrm[3] + e0.w);
        *(float4*)(op + 4) = make_float4(nrm[4] + e1.x, nrm[5] + e1.y, nrm[6] + e1.z, nrm[7] + e1.w);
    }
}

extern "C" void kernel_launch(void* const* d_in, const int* in_sizes, int n_in,
                              void* d_out, int out_size) {
    const float* nf  = (const float*)d_in[0];
    const float* ef  = (const float*)d_in[1];
    const int*   snd = (const int*)d_in[2];
    const int*   rcv = (const int*)d_in[3];
    const float* ew1 = (const float*)d_in[4];
    const float* eb1 = (const float*)d_in[5];
    const float* ew2 = (const float*)d_in[6];
    const float* eb2 = (const float*)d_in[7];
    const float* ew3 = (const float*)d_in[8];
    const float* eb3 = (const float*)d_in[9];
    const float* eg  = (const float*)d_in[10];
    const float* ebt = (const float*)d_in[11];
    const float* nw1 = (const float*)d_in[12];
    const float* nb1 = (const float*)d_in[13];
    const float* nw2 = (const float*)d_in[14];
    const float* nb2 = (const float*)d_in[15];
    const float* nw3 = (const float*)d_in[16];
    const float* nb3 = (const float*)d_in[17];
    const float* ng  = (const float*)d_in[18];
    const float* nbt = (const float*)d_in[19];

    float* out_n = (float*)d_out;
    float* out_e = out_n + (size_t)NN * D;

    cudaFuncSetAttribute(mlp_kernel<true>,  cudaFuncAttributeMaxDynamicSharedMemorySize, SMEM_TOTAL);
    cudaFuncSetAttribute(mlp_kernel<false>, cudaFuncAttributeMaxDynamicSharedMemorySize, SMEM_TOTAL);

    prep_weights<<<612, 256>>>(ew1, ew2, ew3, nw1, nw2, nw3);
    zero_agg_kernel<<<NN * D / 4 / 256, 256>>>();
    mlp_kernel<true><<<NE / 64, 256, SMEM_TOTAL>>>(nf, ef, snd, rcv,
                                                   eb1, eb2, eb3, eg, ebt, out_e);
    mlp_kernel<false><<<(NN + 63) / 64, 256, SMEM_TOTAL>>>(nf, ef, snd, rcv,
                                                           nb1, nb2, nb3, ng, nbt, out_n);
}